// round 1
// baseline (speedup 1.0000x reference)
#include <cuda_runtime.h>
#include <cuda_bf16.h>
#include <math.h>

#define HID 768
#define NSPLITS 12
#define H 6
#define D 64
#define AH 384
#define KS 9
#define PAD 4
#define BB 4
#define S 1024
#define OUT_W 768

// ---------------- scratch (device globals; no allocation allowed) ----------------
__device__ float g_scores[(size_t)BB * H * S * S];     // 25.2M floats, reused for probs
__device__ float g_mq[(size_t)BB * S * AH];
__device__ float g_mk[(size_t)BB * S * AH];
__device__ float g_mv[(size_t)BB * S * AH];
__device__ float g_co[(size_t)BB * S * AH];
__device__ float g_convattn[(size_t)BB * S * AH];
__device__ float g_dw[(size_t)BB * S * HID];
__device__ float g_ck[(size_t)BB * S * H * KS];
__device__ float g_tdsm[(size_t)BB * S];

// ---------------- generic tiled SGEMM ----------------
// C[m,n] = alpha * sum_k A[m,k]*B[k,n]  (BT=false)  or  A[m,k]*B[n,k] (BT=true)
// then (+ bias[n]) then (* mul[m,n]).
// Batched over blockIdx.z: ptr += (z/zdiv)*s?1 + (z%zdiv)*s?2
#define TM 64
#define TN 64
#define TKK 16

template<bool BT>
__global__ void sgemm_kernel(const float* __restrict__ A, const float* __restrict__ Bm,
                             const float* __restrict__ bias, const float* __restrict__ mul,
                             float* __restrict__ C,
                             int M, int N, int K, int lda, int ldb, int ldc,
                             long long sA1, long long sA2,
                             long long sB1, long long sB2,
                             long long sC1, long long sC2, int zdiv,
                             float alpha)
{
    int z = blockIdx.z;
    int zb = z / zdiv, zh = z % zdiv;
    A  += zb * sA1 + zh * sA2;
    Bm += zb * sB1 + zh * sB2;
    C  += zb * sC1 + zh * sC2;

    __shared__ float As[TKK][TM + 1];
    __shared__ float Bs[TKK][TN + 1];

    const int tx = threadIdx.x;          // 0..255
    const int tr = tx >> 4, tc = tx & 15;
    const int m0 = blockIdx.y * TM;
    const int n0 = blockIdx.x * TN;

    float acc[4][4];
#pragma unroll
    for (int i = 0; i < 4; i++)
#pragma unroll
        for (int j = 0; j < 4; j++) acc[i][j] = 0.f;

    for (int k0 = 0; k0 < K; k0 += TKK) {
#pragma unroll
        for (int i = 0; i < 4; i++) {
            int idx = tx + i * 256;
            int am_ = idx / TKK, ak = idx % TKK;
            int gm = m0 + am_, gk = k0 + ak;
            As[ak][am_] = (gm < M && gk < K) ? A[(long long)gm * lda + gk] : 0.f;
        }
#pragma unroll
        for (int i = 0; i < 4; i++) {
            int idx = tx + i * 256;
            int bk = idx / TN, bn = idx % TN;
            int gk = k0 + bk, gn = n0 + bn;
            float v = 0.f;
            if (gk < K && gn < N)
                v = BT ? Bm[(long long)gn * ldb + gk] : Bm[(long long)gk * ldb + gn];
            Bs[bk][bn] = v;
        }
        __syncthreads();
#pragma unroll
        for (int kk = 0; kk < TKK; kk++) {
            float a[4], bv[4];
#pragma unroll
            for (int i = 0; i < 4; i++) a[i] = As[kk][tr * 4 + i];
#pragma unroll
            for (int j = 0; j < 4; j++) bv[j] = Bs[kk][tc * 4 + j];
#pragma unroll
            for (int i = 0; i < 4; i++)
#pragma unroll
                for (int j = 0; j < 4; j++) acc[i][j] = fmaf(a[i], bv[j], acc[i][j]);
        }
        __syncthreads();
    }

#pragma unroll
    for (int i = 0; i < 4; i++) {
        int gm = m0 + tr * 4 + i;
        if (gm >= M) continue;
#pragma unroll
        for (int j = 0; j < 4; j++) {
            int gn = n0 + tc * 4 + j;
            if (gn >= N) continue;
            float v = acc[i][j] * alpha;
            if (bias) v += bias[gn];
            if (mul)  v *= mul[(long long)gm * ldc + gn];
            C[(long long)gm * ldc + gn] = v;
        }
    }
}

// ---------------- depthwise conv over sequence dim ----------------
__global__ void dw_kernel(const float* __restrict__ Kin, const float* __restrict__ dw_w)
{
    long long idx = (long long)blockIdx.x * blockDim.x + threadIdx.x;
    if (idx >= (long long)BB * S * HID) return;
    int c  = (int)(idx % HID);
    long long bs = idx / HID;
    int s = (int)(bs % S);
    int b = (int)(bs / S);
    const float* kb = Kin + (long long)b * S * HID;
    float acc = 0.f;
#pragma unroll
    for (int t = 0; t < KS; t++) {
        int sp = s + t - PAD;
        if (sp >= 0 && sp < S) acc = fmaf(kb[(long long)sp * HID + c], dw_w[c * KS + t], acc);
    }
    g_dw[idx] = acc;
}

// ---------------- td softmax (row-independent!) ----------------
__global__ void tdsm_kernel(const float* __restrict__ td, const int* __restrict__ mask)
{
    __shared__ float sred[8];
    const int b = blockIdx.x;
    const int t = threadIdx.x;            // 256 threads, 4 each
    const int lane = t & 31, wid = t >> 5;
    const int j0 = t * 4;
    const float* tr = td + b * S;
    const int* mr = mask + b * S;

    float v[4]; int am[4];
#pragma unroll
    for (int u = 0; u < 4; u++) { v[u] = tr[j0 + u]; am[u] = mr[j0 + u] != 0; }

    // norm over full row
    float ss = 0.f;
#pragma unroll
    for (int u = 0; u < 4; u++) ss += v[u] * v[u];
#pragma unroll
    for (int o = 16; o; o >>= 1) ss += __shfl_xor_sync(0xffffffffu, ss, o);
    if (lane == 0) sred[wid] = ss;
    __syncthreads();
    if (wid == 0) {
        float w = (lane < 8) ? sred[lane] : 0.f;
#pragma unroll
        for (int o = 4; o; o >>= 1) w += __shfl_xor_sync(0xffffffffu, w, o);
        if (lane == 0) sred[0] = w;
    }
    __syncthreads();
    float nrm = sqrtf(sred[0]);
    float inv = 1.f / fmaxf(nrm, 1e-12f);
    __syncthreads();

    float x[4];
#pragma unroll
    for (int u = 0; u < 4; u++) x[u] = am[u] ? v[u] * inv : -1e4f;

    // softmax over 1024
    float mx = fmaxf(fmaxf(x[0], x[1]), fmaxf(x[2], x[3]));
#pragma unroll
    for (int o = 16; o; o >>= 1) mx = fmaxf(mx, __shfl_xor_sync(0xffffffffu, mx, o));
    if (lane == 0) sred[wid] = mx;
    __syncthreads();
    if (wid == 0) {
        float w = (lane < 8) ? sred[lane] : -1e30f;
#pragma unroll
        for (int o = 4; o; o >>= 1) w = fmaxf(w, __shfl_xor_sync(0xffffffffu, w, o));
        if (lane == 0) sred[0] = w;
    }
    __syncthreads();
    mx = sred[0];
    __syncthreads();

    float e[4], le = 0.f;
#pragma unroll
    for (int u = 0; u < 4; u++) { e[u] = expf(x[u] - mx); le += e[u]; }
#pragma unroll
    for (int o = 16; o; o >>= 1) le += __shfl_xor_sync(0xffffffffu, le, o);
    if (lane == 0) sred[wid] = le;
    __syncthreads();
    if (wid == 0) {
        float w = (lane < 8) ? sred[lane] : 0.f;
#pragma unroll
        for (int o = 4; o; o >>= 1) w += __shfl_xor_sync(0xffffffffu, w, o);
        if (lane == 0) sred[0] = w;
    }
    __syncthreads();
    float dinv = 1.f / sred[0];
#pragma unroll
    for (int u = 0; u < 4; u++) g_tdsm[b * S + j0 + u] = e[u] * dinv;
}

// ---------------- fused per-row score pipeline ----------------
// one block per (b,h,i) row of the score matrix; in-place scores -> probs
__device__ __forceinline__ float blockMax256(float v, float* sm, int lane, int wid)
{
#pragma unroll
    for (int o = 16; o; o >>= 1) v = fmaxf(v, __shfl_xor_sync(0xffffffffu, v, o));
    if (lane == 0) sm[wid] = v;
    __syncthreads();
    if (wid == 0) {
        float w = (lane < 8) ? sm[lane] : -3e38f;
#pragma unroll
        for (int o = 4; o; o >>= 1) w = fmaxf(w, __shfl_xor_sync(0xffffffffu, w, o));
        if (lane == 0) sm[0] = w;
    }
    __syncthreads();
    float r = sm[0];
    __syncthreads();
    return r;
}

__device__ __forceinline__ float blockSum256(float v, float* sm, int lane, int wid)
{
#pragma unroll
    for (int o = 16; o; o >>= 1) v += __shfl_xor_sync(0xffffffffu, v, o);
    if (lane == 0) sm[wid] = v;
    __syncthreads();
    if (wid == 0) {
        float w = (lane < 8) ? sm[lane] : 0.f;
#pragma unroll
        for (int o = 4; o; o >>= 1) w += __shfl_xor_sync(0xffffffffu, w, o);
        if (lane == 0) sm[0] = w;
    }
    __syncthreads();
    float r = sm[0];
    __syncthreads();
    return r;
}

__global__ void row_pipeline_kernel(const int* __restrict__ mask,
                                    const float* __restrict__ gammas)
{
    __shared__ float sred[8];
    __shared__ float swarp[8];
    const int t = threadIdx.x;
    const int lane = t & 31, wid = t >> 5;
    const int row = blockIdx.x;              // (b*H + h)*S + i
    const int i  = row & (S - 1);
    const int bh = row >> 10;
    const int h  = bh % H;
    const int b  = bh / H;
    float* srow = g_scores + (size_t)row * S;
    const int j0 = t * 4;

    float4 x4 = *reinterpret_cast<const float4*>(srow + j0);
    float x[4] = { x4.x, x4.y, x4.z, x4.w };
    const int* mr = mask + b * S;
    int am[4];
#pragma unroll
    for (int u = 0; u < 4; u++) am[u] = mr[j0 + u] != 0;
    float xm[4];
#pragma unroll
    for (int u = 0; u < 4; u++) xm[u] = am[u] ? x[u] : -1e8f;

    // softmax #1 -> p (zeroed where masked)
    float mx = fmaxf(fmaxf(xm[0], xm[1]), fmaxf(xm[2], xm[3]));
    mx = blockMax256(mx, sred, lane, wid);
    float e[4], le = 0.f;
#pragma unroll
    for (int u = 0; u < 4; u++) { e[u] = expf(xm[u] - mx); le += e[u]; }
    float denom = blockSum256(le, sred, lane, wid);
    float inv = 1.f / denom;
    float p[4];
#pragma unroll
    for (int u = 0; u < 4; u++) p[u] = am[u] ? e[u] * inv : 0.f;

    // inclusive cumsum of p across the row
    float lp[4]; float run = 0.f;
#pragma unroll
    for (int u = 0; u < 4; u++) { run += p[u]; lp[u] = run; }
    float tot = run;
    float sc = tot;
#pragma unroll
    for (int o = 1; o < 32; o <<= 1) {
        float v = __shfl_up_sync(0xffffffffu, sc, o);
        if (lane >= o) sc += v;
    }
    if (lane == 31) swarp[wid] = sc;
    __syncthreads();
    if (wid == 0) {
        float v = (lane < 8) ? swarp[lane] : 0.f;
#pragma unroll
        for (int o = 1; o < 8; o <<= 1) {
            float w = __shfl_up_sync(0xffffffffu, v, o);
            if (lane >= o) v += w;
        }
        if (lane < 8) swarp[lane] = v;
    }
    __syncthreads();
    float off = ((wid > 0) ? swarp[wid - 1] : 0.f) + (sc - tot);
    float total = swarp[7];
    __syncthreads();

    // distance decay + td effect
    const float g0 = gammas[h];
    const float gamma = -(g0 > 20.f ? g0 : log1pf(expf(g0)));
    const float* tdr = g_tdsm + b * S;

    float y[4];
#pragma unroll
    for (int u = 0; u < 4; u++) {
        int j = j0 + u;
        float cum = off + lp[u];
        float rem = total - cum;
        float pos = fabsf((float)(j - i));
        float ds = sqrtf(fmaxf(rem * pos, 0.f));
        float te = expf(ds * gamma);
        te = fminf(fmaxf(te, 1e-5f), 1e5f);
        float tef = te - ((j < i) ? tdr[j] : 0.f);
        y[u] = am[u] ? x[u] * tef : -1e8f;
    }

    // softmax #2 -> probs, in place
    float mx2 = fmaxf(fmaxf(y[0], y[1]), fmaxf(y[2], y[3]));
    mx2 = blockMax256(mx2, sred, lane, wid);
    float e2[4], le2 = 0.f;
#pragma unroll
    for (int u = 0; u < 4; u++) { e2[u] = expf(y[u] - mx2); le2 += e2[u]; }
    float denom2 = blockSum256(le2, sred, lane, wid);
    float inv2 = 1.f / denom2;
    float4 o4;
    o4.x = e2[0] * inv2; o4.y = e2[1] * inv2; o4.z = e2[2] * inv2; o4.w = e2[3] * inv2;
    *reinterpret_cast<float4*>(srow + j0) = o4;
}

// ---------------- dynamic span conv output (second half of d_out) ----------------
__global__ void convout_kernel(float* __restrict__ out)
{
    __shared__ float s_log[H * KS];
    __shared__ float s_ck[H * KS];
    const int bs = blockIdx.x;               // b*S + s
    const int b = bs >> 10, s = bs & (S - 1);
    const int t = threadIdx.x;               // 384
    if (t < H * KS) s_log[t] = g_ck[(size_t)bs * (H * KS) + t];
    __syncthreads();
    if (t < H) {
        float mx = -3e38f;
#pragma unroll
        for (int k = 0; k < KS; k++) mx = fmaxf(mx, s_log[t * KS + k]);
        float sum = 0.f, ev[KS];
#pragma unroll
        for (int k = 0; k < KS; k++) { ev[k] = expf(s_log[t * KS + k] - mx); sum += ev[k]; }
        float inv = 1.f / sum;
#pragma unroll
        for (int k = 0; k < KS; k++) s_ck[t * KS + k] = ev[k] * inv;
    }
    __syncthreads();
    const int h = t >> 6;
    float acc = 0.f;
#pragma unroll
    for (int k = 0; k < KS; k++) {
        int sp = s + k - PAD;
        if (sp >= 0 && sp < S)
            acc = fmaf(s_ck[h * KS + k], g_co[((size_t)b * S + sp) * AH + t], acc);
    }
    out[((size_t)b * S + s) * OUT_W + AH + t] = acc;
}

// ---------------- launcher ----------------
static inline void run_gemm(bool bt, const float* A, const float* Bm,
                            const float* bias, const float* mul, float* C,
                            int M, int N, int K, int lda, int ldb, int ldc,
                            long long sA1, long long sA2, long long sB1, long long sB2,
                            long long sC1, long long sC2, int zdiv, int batches, float alpha)
{
    dim3 grid((N + TN - 1) / TN, (M + TM - 1) / TM, batches);
    if (bt)
        sgemm_kernel<true><<<grid, 256>>>(A, Bm, bias, mul, C, M, N, K, lda, ldb, ldc,
                                          sA1, sA2, sB1, sB2, sC1, sC2, zdiv, alpha);
    else
        sgemm_kernel<false><<<grid, 256>>>(A, Bm, bias, mul, C, M, N, K, lda, ldb, ldc,
                                           sA1, sA2, sB1, sB2, sC1, sC2, zdiv, alpha);
}

extern "C" void kernel_launch(void* const* d_in, const int* in_sizes, int n_in,
                              void* d_out, int out_size)
{
    const float* Q    = (const float*)d_in[0];
    const float* Kin  = (const float*)d_in[1];
    const float* V    = (const float*)d_in[2];
    const float* td   = (const float*)d_in[3];
    const int*   mask = (const int*)  d_in[4];
    const float* Wq   = (const float*)d_in[5];
    const float* Wk   = (const float*)d_in[6];
    const float* Wv   = (const float*)d_in[7];
    const float* dw_w = (const float*)d_in[8];
    const float* pw_w = (const float*)d_in[9];
    const float* sep_b= (const float*)d_in[10];
    const float* ck_W = (const float*)d_in[11];
    const float* ck_b = (const float*)d_in[12];
    const float* co_W = (const float*)d_in[13];
    const float* co_b = (const float*)d_in[14];
    const float* gammas=(const float*)d_in[15];
    float* out = (float*)d_out;

    float *p_scores, *p_mq, *p_mk, *p_mv, *p_co, *p_ca, *p_dw, *p_ck;
    cudaGetSymbolAddress((void**)&p_scores, g_scores);
    cudaGetSymbolAddress((void**)&p_mq, g_mq);
    cudaGetSymbolAddress((void**)&p_mk, g_mk);
    cudaGetSymbolAddress((void**)&p_mv, g_mv);
    cudaGetSymbolAddress((void**)&p_co, g_co);
    cudaGetSymbolAddress((void**)&p_ca, g_convattn);
    cudaGetSymbolAddress((void**)&p_dw, g_dw);
    cudaGetSymbolAddress((void**)&p_ck, g_ck);

    const int M = BB * S;

    // projections
    run_gemm(false, Q,   Wq,   nullptr, nullptr, p_mq, M, AH, HID, HID, AH, AH, 0,0,0,0,0,0, 1, 1, 1.f);
    run_gemm(false, Kin, Wk,   nullptr, nullptr, p_mk, M, AH, HID, HID, AH, AH, 0,0,0,0,0,0, 1, 1, 1.f);
    run_gemm(false, V,   Wv,   nullptr, nullptr, p_mv, M, AH, HID, HID, AH, AH, 0,0,0,0,0,0, 1, 1, 1.f);
    run_gemm(false, V,   co_W, co_b,    nullptr, p_co, M, AH, HID, HID, AH, AH, 0,0,0,0,0,0, 1, 1, 1.f);

    // separable conv: depthwise then pointwise (fused with *mq -> conv_attn)
    {
        long long n = (long long)BB * S * HID;
        dw_kernel<<<(unsigned)((n + 255) / 256), 256>>>(Kin, dw_w);
    }
    run_gemm(true, p_dw, pw_w, sep_b, p_mq, p_ca, M, AH, HID, HID, HID, AH, 0,0,0,0,0,0, 1, 1, 1.f);

    // conv kernel layer + conv out
    run_gemm(false, p_ca, ck_W, ck_b, nullptr, p_ck, M, H * KS, AH, AH, H * KS, H * KS, 0,0,0,0,0,0, 1, 1, 1.f);
    convout_kernel<<<BB * S, AH>>>(out);

    // td softmax (row-independent)
    tdsm_kernel<<<BB, 256>>>(td, mask);

    // attention scores (batched over b,h)
    run_gemm(true, p_mq, p_mk, nullptr, nullptr, p_scores,
             S, S, D, AH, AH, S,
             (long long)S * AH, (long long)D,
             (long long)S * AH, (long long)D,
             (long long)H * S * S, (long long)S * S,
             H, BB * H, 0.125f);

    // fused dist_func + double softmax, in place
    row_pipeline_kernel<<<BB * H * S, 256>>>(mask, gammas);

    // ctx = probs @ v, written straight into first half of d_out
    run_gemm(false, p_scores, p_mv, nullptr, nullptr, out + 0,
             S, D, S, S, AH, OUT_W,
             (long long)H * S * S, (long long)S * S,
             (long long)S * AH, (long long)D,
             (long long)S * OUT_W, (long long)D,
             H, BB * H, 1.f);
}

// round 4
// speedup vs baseline: 1.6609x; 1.6609x over previous
#include <cuda_runtime.h>
#include <cuda_bf16.h>
#include <math.h>

#define HID 768
#define NSPLITS 12
#define H 6
#define D 64
#define AH 384
#define KS 9
#define PAD 4
#define BB 4
#define S 1024
#define OUT_W 768

// ---------------- scratch (device globals; no allocation allowed) ----------------
__device__ float g_scores[(size_t)BB * H * S * S];     // reused for probs
__device__ float g_mq[(size_t)BB * S * AH];
__device__ float g_mk[(size_t)BB * S * AH];
__device__ float g_mv[(size_t)BB * S * AH];
__device__ float g_co[(size_t)BB * S * AH];
__device__ float g_convattn[(size_t)BB * S * AH];
__device__ float g_dw[(size_t)BB * S * HID];
__device__ float g_ck[(size_t)BB * S * H * KS];
__device__ float g_tdsm[(size_t)BB * S];

// ---------------- TF32 tensor-core GEMM ----------------
// C[m,n] = alpha * sum_k A[m,k]*B[k,n]  (BT=false)  or  A[m,k]*B[n,k] (BT=true)
// then (+ bias[n]) then (* mul[m,n]).  Batched over blockIdx.z.
// Block tile 64x64, K-step 32, 4 warps (each 32x32 via m16n8k8).

__device__ __forceinline__ unsigned f2tf32(float x) {
    unsigned y;
    asm("cvt.rna.tf32.f32 %0, %1;" : "=r"(y) : "f"(x));
    return y;
}

__device__ __forceinline__ void mma8(float* c, const unsigned* a, const unsigned* b) {
    asm volatile("mma.sync.aligned.m16n8k8.row.col.f32.tf32.tf32.f32 "
        "{%0,%1,%2,%3},{%4,%5,%6,%7},{%8,%9},{%0,%1,%2,%3};"
        : "+f"(c[0]), "+f"(c[1]), "+f"(c[2]), "+f"(c[3])
        : "r"(a[0]), "r"(a[1]), "r"(a[2]), "r"(a[3]), "r"(b[0]), "r"(b[1]));
}

#define BM 64
#define BN 64
#define BK 32
#define AS_LD 36   // m-major A: [64][36]
#define BS_LD 72   // k-major B: [32][72]  (same 2304-word footprint as [64][36])

template<bool BT>
__global__ __launch_bounds__(128) void tf32_gemm(
    const float* __restrict__ A, const float* __restrict__ Bm,
    const float* __restrict__ bias, const float* __restrict__ mul,
    float* __restrict__ C,
    int M, int N, int K, int lda, int ldb, int ldc,
    long long sA1, long long sA2,
    long long sB1, long long sB2,
    long long sC1, long long sC2, int zdiv,
    float alpha)
{
    int z = blockIdx.z;
    int zb = z / zdiv, zh = z % zdiv;
    A  += zb * sA1 + zh * sA2;
    Bm += zb * sB1 + zh * sB2;
    C  += zb * sC1 + zh * sC2;

    __shared__ unsigned As[BM * AS_LD];       // [m][k] m-major, 9216 B
    __shared__ unsigned Bs[BM * AS_LD];       // BT: [n][k] n-major ; !BT: [k][n] k-major (BS_LD)

    const int tid  = threadIdx.x;
    const int warp = tid >> 5, lane = tid & 31;
    const int g    = lane >> 2, tig = lane & 3;
    const int wm   = (warp >> 1) * 32, wn = (warp & 1) * 32;
    const int m0   = blockIdx.y * BM;
    const int n0   = blockIdx.x * BN;

    float acc[2][4][4];
#pragma unroll
    for (int mt = 0; mt < 2; mt++)
#pragma unroll
        for (int nt = 0; nt < 4; nt++)
#pragma unroll
            for (int e = 0; e < 4; e++) acc[mt][nt][e] = 0.f;

    for (int k0 = 0; k0 < K; k0 += BK) {
        // ---- A tile: coalesced float4 along k, store m-major (STS.128, conflict-free)
#pragma unroll
        for (int it = 0; it < 4; it++) {
            int lin = tid + it * 128;
            int m = lin >> 3, kq = lin & 7;
            const float4 v = *reinterpret_cast<const float4*>(
                A + (long long)(m0 + m) * lda + k0 + kq * 4);
            uint4 w;
            w.x = f2tf32(v.x); w.y = f2tf32(v.y); w.z = f2tf32(v.z); w.w = f2tf32(v.w);
            *reinterpret_cast<uint4*>(&As[m * AS_LD + kq * 4]) = w;
        }
        // ---- B tile
        if (BT) {
#pragma unroll
            for (int it = 0; it < 4; it++) {
                int lin = tid + it * 128;
                int n = lin >> 3, kq = lin & 7;
                const float4 v = *reinterpret_cast<const float4*>(
                    Bm + (long long)(n0 + n) * ldb + k0 + kq * 4);
                uint4 w;
                w.x = f2tf32(v.x); w.y = f2tf32(v.y); w.z = f2tf32(v.z); w.w = f2tf32(v.w);
                *reinterpret_cast<uint4*>(&Bs[n * AS_LD + kq * 4]) = w;
            }
        } else {
            // tile is BK(32) x BN(64) = 512 float4 quads, 16 quads per k-row
#pragma unroll
            for (int it = 0; it < 4; it++) {
                int lin = tid + it * 128;
                int k = lin >> 4, nq = lin & 15;
                int gn = n0 + nq * 4;
                if (((ldb & 3) == 0) && (gn + 3 < N)) {
                    const float4 v = *reinterpret_cast<const float4*>(
                        Bm + (long long)(k0 + k) * ldb + gn);
                    uint4 w;
                    w.x = f2tf32(v.x); w.y = f2tf32(v.y); w.z = f2tf32(v.z); w.w = f2tf32(v.w);
                    *reinterpret_cast<uint4*>(&Bs[k * BS_LD + nq * 4]) = w;
                } else {
#pragma unroll
                    for (int r = 0; r < 4; r++)
                        Bs[k * BS_LD + nq * 4 + r] =
                            (gn + r < N) ? f2tf32(Bm[(long long)(k0 + k) * ldb + gn + r]) : 0u;
                }
            }
        }
        __syncthreads();

#pragma unroll
        for (int kk = 0; kk < 4; kk++) {
            const int kb = kk * 8;
            unsigned aF[2][4], bF[4][2];
#pragma unroll
            for (int mt = 0; mt < 2; mt++) {
                int mr = wm + mt * 16 + g;
                aF[mt][0] = As[mr * AS_LD + kb + tig];
                aF[mt][1] = As[(mr + 8) * AS_LD + kb + tig];
                aF[mt][2] = As[mr * AS_LD + kb + tig + 4];
                aF[mt][3] = As[(mr + 8) * AS_LD + kb + tig + 4];
            }
#pragma unroll
            for (int nt = 0; nt < 4; nt++) {
                int nc = wn + nt * 8 + g;
                if (BT) {
                    bF[nt][0] = Bs[nc * AS_LD + kb + tig];
                    bF[nt][1] = Bs[nc * AS_LD + kb + tig + 4];
                } else {
                    bF[nt][0] = Bs[(kb + tig) * BS_LD + nc];
                    bF[nt][1] = Bs[(kb + tig + 4) * BS_LD + nc];
                }
            }
#pragma unroll
            for (int mt = 0; mt < 2; mt++)
#pragma unroll
                for (int nt = 0; nt < 4; nt++)
                    mma8(acc[mt][nt], aF[mt], bF[nt]);
        }
        __syncthreads();
    }

    // ---- epilogue
#pragma unroll
    for (int mt = 0; mt < 2; mt++) {
#pragma unroll
        for (int nt = 0; nt < 4; nt++) {
            int gm0 = m0 + wm + mt * 16 + g;
            int gn0 = n0 + wn + nt * 8 + tig * 2;
            float* c = acc[mt][nt];
#pragma unroll
            for (int e = 0; e < 4; e++) {
                int gm = gm0 + (e >> 1) * 8;
                int gn = gn0 + (e & 1);
                if (gn < N) {
                    float v = c[e] * alpha;
                    if (bias) v += bias[gn];
                    if (mul)  v *= mul[(long long)gm * ldc + gn];
                    C[(long long)gm * ldc + gn] = v;
                }
            }
        }
    }
}

// ---------------- depthwise conv over sequence dim ----------------
__global__ void dw_kernel(const float* __restrict__ Kin, const float* __restrict__ dw_w)
{
    long long idx = (long long)blockIdx.x * blockDim.x + threadIdx.x;
    if (idx >= (long long)BB * S * HID) return;
    int c  = (int)(idx % HID);
    long long bs = idx / HID;
    int s = (int)(bs % S);
    int b = (int)(bs / S);
    const float* kb = Kin + (long long)b * S * HID;
    float acc = 0.f;
#pragma unroll
    for (int t = 0; t < KS; t++) {
        int sp = s + t - PAD;
        if (sp >= 0 && sp < S) acc = fmaf(kb[(long long)sp * HID + c], dw_w[c * KS + t], acc);
    }
    g_dw[idx] = acc;
}

// ---------------- td softmax (row-independent) ----------------
__global__ void tdsm_kernel(const float* __restrict__ td, const int* __restrict__ mask)
{
    __shared__ float sred[8];
    const int b = blockIdx.x;
    const int t = threadIdx.x;            // 256 threads, 4 each
    const int lane = t & 31, wid = t >> 5;
    const int j0 = t * 4;
    const float* tr = td + b * S;
    const int* mr = mask + b * S;

    float v[4]; int am[4];
#pragma unroll
    for (int u = 0; u < 4; u++) { v[u] = tr[j0 + u]; am[u] = mr[j0 + u] != 0; }

    float ss = 0.f;
#pragma unroll
    for (int u = 0; u < 4; u++) ss += v[u] * v[u];
#pragma unroll
    for (int o = 16; o; o >>= 1) ss += __shfl_xor_sync(0xffffffffu, ss, o);
    if (lane == 0) sred[wid] = ss;
    __syncthreads();
    if (wid == 0) {
        float w = (lane < 8) ? sred[lane] : 0.f;
#pragma unroll
        for (int o = 4; o; o >>= 1) w += __shfl_xor_sync(0xffffffffu, w, o);
        if (lane == 0) sred[0] = w;
    }
    __syncthreads();
    float nrm = sqrtf(sred[0]);
    float inv = 1.f / fmaxf(nrm, 1e-12f);
    __syncthreads();

    float x[4];
#pragma unroll
    for (int u = 0; u < 4; u++) x[u] = am[u] ? v[u] * inv : -1e4f;

    float mx = fmaxf(fmaxf(x[0], x[1]), fmaxf(x[2], x[3]));
#pragma unroll
    for (int o = 16; o; o >>= 1) mx = fmaxf(mx, __shfl_xor_sync(0xffffffffu, mx, o));
    if (lane == 0) sred[wid] = mx;
    __syncthreads();
    if (wid == 0) {
        float w = (lane < 8) ? sred[lane] : -1e30f;
#pragma unroll
        for (int o = 4; o; o >>= 1) w = fmaxf(w, __shfl_xor_sync(0xffffffffu, w, o));
        if (lane == 0) sred[0] = w;
    }
    __syncthreads();
    mx = sred[0];
    __syncthreads();

    float e[4], le = 0.f;
#pragma unroll
    for (int u = 0; u < 4; u++) { e[u] = expf(x[u] - mx); le += e[u]; }
#pragma unroll
    for (int o = 16; o; o >>= 1) le += __shfl_xor_sync(0xffffffffu, le, o);
    if (lane == 0) sred[wid] = le;
    __syncthreads();
    if (wid == 0) {
        float w = (lane < 8) ? sred[lane] : 0.f;
#pragma unroll
        for (int o = 4; o; o >>= 1) w += __shfl_xor_sync(0xffffffffu, w, o);
        if (lane == 0) sred[0] = w;
    }
    __syncthreads();
    float dinv = 1.f / sred[0];
#pragma unroll
    for (int u = 0; u < 4; u++) g_tdsm[b * S + j0 + u] = e[u] * dinv;
}

// ---------------- fused per-row score pipeline ----------------
__device__ __forceinline__ float blockMax256(float v, float* sm, int lane, int wid)
{
#pragma unroll
    for (int o = 16; o; o >>= 1) v = fmaxf(v, __shfl_xor_sync(0xffffffffu, v, o));
    if (lane == 0) sm[wid] = v;
    __syncthreads();
    if (wid == 0) {
        float w = (lane < 8) ? sm[lane] : -3e38f;
#pragma unroll
        for (int o = 4; o; o >>= 1) w = fmaxf(w, __shfl_xor_sync(0xffffffffu, w, o));
        if (lane == 0) sm[0] = w;
    }
    __syncthreads();
    float r = sm[0];
    __syncthreads();
    return r;
}

__device__ __forceinline__ float blockSum256(float v, float* sm, int lane, int wid)
{
#pragma unroll
    for (int o = 16; o; o >>= 1) v += __shfl_xor_sync(0xffffffffu, v, o);
    if (lane == 0) sm[wid] = v;
    __syncthreads();
    if (wid == 0) {
        float w = (lane < 8) ? sm[lane] : 0.f;
#pragma unroll
        for (int o = 4; o; o >>= 1) w += __shfl_xor_sync(0xffffffffu, w, o);
        if (lane == 0) sm[0] = w;
    }
    __syncthreads();
    float r = sm[0];
    __syncthreads();
    return r;
}

__global__ void row_pipeline_kernel(const int* __restrict__ mask,
                                    const float* __restrict__ gammas)
{
    __shared__ float sred[8];
    __shared__ float swarp[8];
    const int t = threadIdx.x;
    const int lane = t & 31, wid = t >> 5;
    const int row = blockIdx.x;              // (b*H + h)*S + i
    const int i  = row & (S - 1);
    const int bh = row >> 10;
    const int h  = bh % H;
    const int b  = bh / H;
    float* srow = g_scores + (size_t)row * S;
    const int j0 = t * 4;

    float4 x4 = *reinterpret_cast<const float4*>(srow + j0);
    float x[4] = { x4.x, x4.y, x4.z, x4.w };
    const int* mr = mask + b * S;
    int am[4];
#pragma unroll
    for (int u = 0; u < 4; u++) am[u] = mr[j0 + u] != 0;
    float xm[4];
#pragma unroll
    for (int u = 0; u < 4; u++) xm[u] = am[u] ? x[u] : -1e8f;

    float mx = fmaxf(fmaxf(xm[0], xm[1]), fmaxf(xm[2], xm[3]));
    mx = blockMax256(mx, sred, lane, wid);
    float e[4], le = 0.f;
#pragma unroll
    for (int u = 0; u < 4; u++) { e[u] = expf(xm[u] - mx); le += e[u]; }
    float denom = blockSum256(le, sred, lane, wid);
    float inv = 1.f / denom;
    float p[4];
#pragma unroll
    for (int u = 0; u < 4; u++) p[u] = am[u] ? e[u] * inv : 0.f;

    float lp[4]; float run = 0.f;
#pragma unroll
    for (int u = 0; u < 4; u++) { run += p[u]; lp[u] = run; }
    float tot = run;
    float sc = tot;
#pragma unroll
    for (int o = 1; o < 32; o <<= 1) {
        float v = __shfl_up_sync(0xffffffffu, sc, o);
        if (lane >= o) sc += v;
    }
    if (lane == 31) swarp[wid] = sc;
    __syncthreads();
    if (wid == 0) {
        float v = (lane < 8) ? swarp[lane] : 0.f;
#pragma unroll
        for (int o = 1; o < 8; o <<= 1) {
            float w = __shfl_up_sync(0xffffffffu, v, o);
            if (lane >= o) v += w;
        }
        if (lane < 8) swarp[lane] = v;
    }
    __syncthreads();
    float off = ((wid > 0) ? swarp[wid - 1] : 0.f) + (sc - tot);
    float total = swarp[7];
    __syncthreads();

    const float g0 = gammas[h];
    const float gamma = -(g0 > 20.f ? g0 : log1pf(expf(g0)));
    const float* tdr = g_tdsm + b * S;

    float y[4];
#pragma unroll
    for (int u = 0; u < 4; u++) {
        int j = j0 + u;
        float cum = off + lp[u];
        float rem = total - cum;
        float pos = fabsf((float)(j - i));
        float ds = sqrtf(fmaxf(rem * pos, 0.f));
        float te = expf(ds * gamma);
        te = fminf(fmaxf(te, 1e-5f), 1e5f);
        float tef = te - ((j < i) ? tdr[j] : 0.f);
        y[u] = am[u] ? x[u] * tef : -1e8f;
    }

    float mx2 = fmaxf(fmaxf(y[0], y[1]), fmaxf(y[2], y[3]));
    mx2 = blockMax256(mx2, sred, lane, wid);
    float e2[4], le2 = 0.f;
#pragma unroll
    for (int u = 0; u < 4; u++) { e2[u] = expf(y[u] - mx2); le2 += e2[u]; }
    float denom2 = blockSum256(le2, sred, lane, wid);
    float inv2 = 1.f / denom2;
    float4 o4;
    o4.x = e2[0] * inv2; o4.y = e2[1] * inv2; o4.z = e2[2] * inv2; o4.w = e2[3] * inv2;
    *reinterpret_cast<float4*>(srow + j0) = o4;
}

// ---------------- dynamic span conv output (second half of d_out) ----------------
__global__ void convout_kernel(float* __restrict__ out)
{
    __shared__ float s_log[H * KS];
    __shared__ float s_ck[H * KS];
    const int bs = blockIdx.x;               // b*S + s
    const int b = bs >> 10, s = bs & (S - 1);
    const int t = threadIdx.x;               // 384
    if (t < H * KS) s_log[t] = g_ck[(size_t)bs * (H * KS) + t];
    __syncthreads();
    if (t < H) {
        float mx = -3e38f;
#pragma unroll
        for (int k = 0; k < KS; k++) mx = fmaxf(mx, s_log[t * KS + k]);
        float sum = 0.f, ev[KS];
#pragma unroll
        for (int k = 0; k < KS; k++) { ev[k] = expf(s_log[t * KS + k] - mx); sum += ev[k]; }
        float inv = 1.f / sum;
#pragma unroll
        for (int k = 0; k < KS; k++) s_ck[t * KS + k] = ev[k] * inv;
    }
    __syncthreads();
    const int h = t >> 6;
    float acc = 0.f;
#pragma unroll
    for (int k = 0; k < KS; k++) {
        int sp = s + k - PAD;
        if (sp >= 0 && sp < S)
            acc = fmaf(s_ck[h * KS + k], g_co[((size_t)b * S + sp) * AH + t], acc);
    }
    out[((size_t)b * S + s) * OUT_W + AH + t] = acc;
}

// ---------------- launcher ----------------
static inline void run_gemm(bool bt, const float* A, const float* Bm,
                            const float* bias, const float* mul, float* C,
                            int M, int N, int K, int lda, int ldb, int ldc,
                            long long sA1, long long sA2, long long sB1, long long sB2,
                            long long sC1, long long sC2, int zdiv, int batches, float alpha)
{
    dim3 grid((N + BN - 1) / BN, (M + BM - 1) / BM, batches);
    if (bt)
        tf32_gemm<true><<<grid, 128>>>(A, Bm, bias, mul, C, M, N, K, lda, ldb, ldc,
                                       sA1, sA2, sB1, sB2, sC1, sC2, zdiv, alpha);
    else
        tf32_gemm<false><<<grid, 128>>>(A, Bm, bias, mul, C, M, N, K, lda, ldb, ldc,
                                        sA1, sA2, sB1, sB2, sC1, sC2, zdiv, alpha);
}

extern "C" void kernel_launch(void* const* d_in, const int* in_sizes, int n_in,
                              void* d_out, int out_size)
{
    const float* Q    = (const float*)d_in[0];
    const float* Kin  = (const float*)d_in[1];
    const float* V    = (const float*)d_in[2];
    const float* td   = (const float*)d_in[3];
    const int*   mask = (const int*)  d_in[4];
    const float* Wq   = (const float*)d_in[5];
    const float* Wk   = (const float*)d_in[6];
    const float* Wv   = (const float*)d_in[7];
    const float* dw_w = (const float*)d_in[8];
    const float* pw_w = (const float*)d_in[9];
    const float* sep_b= (const float*)d_in[10];
    const float* ck_W = (const float*)d_in[11];
    const float* ck_b = (const float*)d_in[12];
    const float* co_W = (const float*)d_in[13];
    const float* co_b = (const float*)d_in[14];
    const float* gammas=(const float*)d_in[15];
    float* out = (float*)d_out;

    float *p_scores, *p_mq, *p_mk, *p_mv, *p_co, *p_ca, *p_dw, *p_ck;
    cudaGetSymbolAddress((void**)&p_scores, g_scores);
    cudaGetSymbolAddress((void**)&p_mq, g_mq);
    cudaGetSymbolAddress((void**)&p_mk, g_mk);
    cudaGetSymbolAddress((void**)&p_mv, g_mv);
    cudaGetSymbolAddress((void**)&p_co, g_co);
    cudaGetSymbolAddress((void**)&p_ca, g_convattn);
    cudaGetSymbolAddress((void**)&p_dw, g_dw);
    cudaGetSymbolAddress((void**)&p_ck, g_ck);

    const int M = BB * S;

    // projections
    run_gemm(false, Q,   Wq,   nullptr, nullptr, p_mq, M, AH, HID, HID, AH, AH, 0,0,0,0,0,0, 1, 1, 1.f);
    run_gemm(false, Kin, Wk,   nullptr, nullptr, p_mk, M, AH, HID, HID, AH, AH, 0,0,0,0,0,0, 1, 1, 1.f);
    run_gemm(false, V,   Wv,   nullptr, nullptr, p_mv, M, AH, HID, HID, AH, AH, 0,0,0,0,0,0, 1, 1, 1.f);
    run_gemm(false, V,   co_W, co_b,    nullptr, p_co, M, AH, HID, HID, AH, AH, 0,0,0,0,0,0, 1, 1, 1.f);

    // separable conv: depthwise then pointwise (fused with *mq -> conv_attn)
    {
        long long n = (long long)BB * S * HID;
        dw_kernel<<<(unsigned)((n + 255) / 256), 256>>>(Kin, dw_w);
    }
    run_gemm(true, p_dw, pw_w, sep_b, p_mq, p_ca, M, AH, HID, HID, HID, AH, 0,0,0,0,0,0, 1, 1, 1.f);

    // conv kernel layer + conv out
    run_gemm(false, p_ca, ck_W, ck_b, nullptr, p_ck, M, H * KS, AH, AH, H * KS, H * KS, 0,0,0,0,0,0, 1, 1, 1.f);
    convout_kernel<<<BB * S, AH>>>(out);

    // td softmax (row-independent)
    tdsm_kernel<<<BB, 256>>>(td, mask);

    // attention scores (batched over b,h)
    run_gemm(true, p_mq, p_mk, nullptr, nullptr, p_scores,
             S, S, D, AH, AH, S,
             (long long)S * AH, (long long)D,
             (long long)S * AH, (long long)D,
             (long long)H * S * S, (long long)S * S,
             H, BB * H, 0.125f);

    // fused dist_func + double softmax, in place
    row_pipeline_kernel<<<BB * H * S, 256>>>(mask, gammas);

    // ctx = probs @ v, written straight into first half of d_out
    run_gemm(false, p_scores, p_mv, nullptr, nullptr, out + 0,
             S, D, S, S, AH, OUT_W,
             (long long)H * S * S, (long long)S * S,
             (long long)S * AH, (long long)D,
             (long long)S * OUT_W, (long long)D,
             H, BB * H, 1.f);
}

// round 5
// speedup vs baseline: 2.7650x; 1.6648x over previous
#include <cuda_runtime.h>
#include <cuda_bf16.h>
#include <math.h>

#define HID 768
#define NSPLITS 12
#define H 6
#define D 64
#define AH 384
#define KS 9
#define PAD 4
#define BB 4
#define S 1024
#define OUT_W 768

// ---------------- scratch (device globals; no allocation allowed) ----------------
__device__ float g_scores[(size_t)BB * H * S * S];     // reused for probs
__device__ float g_mq[(size_t)BB * S * AH];
__device__ float g_mk[(size_t)BB * S * AH];
__device__ float g_mv[(size_t)BB * S * AH];
__device__ float g_co[(size_t)BB * S * AH];
__device__ float g_convattn[(size_t)BB * S * AH];
__device__ float g_dw[(size_t)BB * S * HID];
__device__ float g_ck[(size_t)BB * S * H * KS];
__device__ float g_tdsm[(size_t)BB * S];

// ---------------- common helpers ----------------
__device__ __forceinline__ unsigned f2tf32(float x) {
    unsigned y;
    asm("cvt.rna.tf32.f32 %0, %1;" : "=r"(y) : "f"(x));
    return y;
}

__device__ __forceinline__ void mma8(float* c, const unsigned* a, const unsigned* b) {
    asm volatile("mma.sync.aligned.m16n8k8.row.col.f32.tf32.tf32.f32 "
        "{%0,%1,%2,%3},{%4,%5,%6,%7},{%8,%9},{%0,%1,%2,%3};"
        : "+f"(c[0]), "+f"(c[1]), "+f"(c[2]), "+f"(c[3])
        : "r"(a[0]), "r"(a[1]), "r"(a[2]), "r"(a[3]), "r"(b[0]), "r"(b[1]));
}

__device__ __forceinline__ unsigned smem_u32(const void* p) {
    return (unsigned)__cvta_generic_to_shared(p);
}
#define CP16(dst, src) asm volatile("cp.async.ca.shared.global [%0], [%1], 16;" :: "r"(dst), "l"(src))
#define CPCOMMIT()     asm volatile("cp.async.commit_group;")
#define CPWAIT(n)      asm volatile("cp.async.wait_group %0;" :: "n"(n))

// ================= pipelined TF32 GEMM (full-tile fast path) =================
// Requirements: M % 128 == 0, N % 64 == 0, K % 32 == 0, lda/ldb % 4 == 0,
// base pointers + n0/k0 offsets 16B-aligned. 256 threads, BM=128, BN=64, BK=32.
// C = alpha*A@B(^T) (+bias[n]) (*mul[m,n]).
#define PAS_LD 36
#define PBS_LDT 36   // BT: [n][k]
#define PBS_LDN 72   // !BT: [k][n]
#define PA_STG (128 * PAS_LD)   // 4608 floats per stage
#define PB_STG (64 * PBS_LDT)   // 2304 floats per stage
#define PIPE_SMEM ((2 * PA_STG + 2 * PB_STG) * 4)  // 55296 B

template<bool BT>
__device__ __forceinline__ void gemm_core_pipe(
    const float* __restrict__ A, const float* __restrict__ Bm,
    const float* __restrict__ bias, const float* __restrict__ mul,
    float* __restrict__ C, int N, int K, int lda, int ldb, int ldc, float alpha)
{
    extern __shared__ float dyn[];
    float* sA = dyn;                 // [2][PA_STG]
    float* sB = dyn + 2 * PA_STG;    // [2][PB_STG]

    const int tid  = threadIdx.x;
    const int warp = tid >> 5, lane = tid & 31;
    const int g    = lane >> 2, tig = lane & 3;
    const int wm   = (warp >> 1) * 32, wn = (warp & 1) * 32;
    const int m0   = blockIdx.y * 128;
    const int n0   = blockIdx.x * 64;

    float acc[2][4][4];
#pragma unroll
    for (int mt = 0; mt < 2; mt++)
#pragma unroll
        for (int nt = 0; nt < 4; nt++)
#pragma unroll
            for (int e = 0; e < 4; e++) acc[mt][nt][e] = 0.f;

    const int nk = K >> 5;

    // stage loader: A tile 128x32 (1024 quads), B tile 512 quads
    auto loadStage = [&](int ki, int st) {
        const int kbase = ki * 32;
#pragma unroll
        for (int it = 0; it < 4; it++) {
            int lin = tid + it * 256;
            int m = lin >> 3, kq = lin & 7;
            unsigned dst = smem_u32(&sA[st * PA_STG + m * PAS_LD + kq * 4]);
            const float* src = A + (long long)(m0 + m) * lda + kbase + kq * 4;
            CP16(dst, src);
        }
        if (BT) {
#pragma unroll
            for (int it = 0; it < 2; it++) {
                int lin = tid + it * 256;
                int n = lin >> 3, kq = lin & 7;
                unsigned dst = smem_u32(&sB[st * PB_STG + n * PBS_LDT + kq * 4]);
                const float* src = Bm + (long long)(n0 + n) * ldb + kbase + kq * 4;
                CP16(dst, src);
            }
        } else {
#pragma unroll
            for (int it = 0; it < 2; it++) {
                int lin = tid + it * 256;
                int k = lin >> 4, nq = lin & 15;
                unsigned dst = smem_u32(&sB[st * PB_STG + k * PBS_LDN + nq * 4]);
                const float* src = Bm + (long long)(kbase + k) * ldb + n0 + nq * 4;
                CP16(dst, src);
            }
        }
        CPCOMMIT();
    };

    loadStage(0, 0);
    for (int i = 0; i < nk; i++) {
        if (i + 1 < nk) { loadStage(i + 1, (i + 1) & 1); CPWAIT(1); }
        else            { CPWAIT(0); }
        __syncthreads();

        const float* as = &sA[(i & 1) * PA_STG];
        const float* bs = &sB[(i & 1) * PB_STG];
#pragma unroll
        for (int kk = 0; kk < 4; kk++) {
            const int kb = kk * 8;
            unsigned aF[2][4], bF[4][2];
#pragma unroll
            for (int mt = 0; mt < 2; mt++) {
                int mr = wm + mt * 16 + g;
                aF[mt][0] = f2tf32(as[mr * PAS_LD + kb + tig]);
                aF[mt][1] = f2tf32(as[(mr + 8) * PAS_LD + kb + tig]);
                aF[mt][2] = f2tf32(as[mr * PAS_LD + kb + tig + 4]);
                aF[mt][3] = f2tf32(as[(mr + 8) * PAS_LD + kb + tig + 4]);
            }
#pragma unroll
            for (int nt = 0; nt < 4; nt++) {
                int nc = wn + nt * 8 + g;
                if (BT) {
                    bF[nt][0] = f2tf32(bs[nc * PBS_LDT + kb + tig]);
                    bF[nt][1] = f2tf32(bs[nc * PBS_LDT + kb + tig + 4]);
                } else {
                    bF[nt][0] = f2tf32(bs[(kb + tig) * PBS_LDN + nc]);
                    bF[nt][1] = f2tf32(bs[(kb + tig + 4) * PBS_LDN + nc]);
                }
            }
#pragma unroll
            for (int mt = 0; mt < 2; mt++)
#pragma unroll
                for (int nt = 0; nt < 4; nt++)
                    mma8(acc[mt][nt], aF[mt], bF[nt]);
        }
        __syncthreads();
    }

    // epilogue (full tiles)
#pragma unroll
    for (int mt = 0; mt < 2; mt++) {
#pragma unroll
        for (int nt = 0; nt < 4; nt++) {
            int gm0 = m0 + wm + mt * 16 + g;
            int gn0 = n0 + wn + nt * 8 + tig * 2;
            float* c = acc[mt][nt];
#pragma unroll
            for (int e = 0; e < 4; e++) {
                int gm = gm0 + (e >> 1) * 8;
                int gn = gn0 + (e & 1);
                float v = c[e] * alpha;
                if (bias) v += bias[gn];
                if (mul)  v *= mul[(long long)gm * ldc + gn];
                C[(long long)gm * ldc + gn] = v;
            }
        }
    }
}

template<bool BT>
__global__ __launch_bounds__(256) void tf32_gemm_pipe(
    const float* __restrict__ A, const float* __restrict__ Bm,
    const float* __restrict__ bias, const float* __restrict__ mul,
    float* __restrict__ C,
    int N, int K, int lda, int ldb, int ldc,
    long long sA1, long long sA2, long long sB1, long long sB2,
    long long sC1, long long sC2, int zdiv, float alpha)
{
    int z = blockIdx.z;
    int zb = z / zdiv, zh = z % zdiv;
    gemm_core_pipe<BT>(A + zb * sA1 + zh * sA2, Bm + zb * sB1 + zh * sB2,
                       bias, mul, C + zb * sC1 + zh * sC2,
                       N, K, lda, ldb, ldc, alpha);
}

struct Proj4 {
    const float* A[4];
    const float* B[4];
    const float* bias[4];
    float* C[4];
};

__global__ __launch_bounds__(256) void tf32_proj4(Proj4 p, int N, int K, int lda, int ldb, int ldc)
{
    int op = blockIdx.z;
    gemm_core_pipe<false>(p.A[op], p.B[op], p.bias[op], nullptr, p.C[op],
                          N, K, lda, ldb, ldc, 1.f);
}

// ================= legacy checked GEMM (used for the tiny misaligned ck GEMM) ==========
#define BM 64
#define BN 64
#define BK 32
#define AS_LD 36
#define BS_LD 72

template<bool BT>
__global__ __launch_bounds__(128) void tf32_gemm(
    const float* __restrict__ A, const float* __restrict__ Bm,
    const float* __restrict__ bias, const float* __restrict__ mul,
    float* __restrict__ C,
    int M, int N, int K, int lda, int ldb, int ldc,
    long long sA1, long long sA2,
    long long sB1, long long sB2,
    long long sC1, long long sC2, int zdiv,
    float alpha)
{
    int z = blockIdx.z;
    int zb = z / zdiv, zh = z % zdiv;
    A  += zb * sA1 + zh * sA2;
    Bm += zb * sB1 + zh * sB2;
    C  += zb * sC1 + zh * sC2;

    __shared__ unsigned As[BM * AS_LD];
    __shared__ unsigned Bs[BM * AS_LD];

    const int tid  = threadIdx.x;
    const int warp = tid >> 5, lane = tid & 31;
    const int g    = lane >> 2, tig = lane & 3;
    const int wm   = (warp >> 1) * 32, wn = (warp & 1) * 32;
    const int m0   = blockIdx.y * BM;
    const int n0   = blockIdx.x * BN;

    float acc[2][4][4];
#pragma unroll
    for (int mt = 0; mt < 2; mt++)
#pragma unroll
        for (int nt = 0; nt < 4; nt++)
#pragma unroll
            for (int e = 0; e < 4; e++) acc[mt][nt][e] = 0.f;

    for (int k0 = 0; k0 < K; k0 += BK) {
#pragma unroll
        for (int it = 0; it < 4; it++) {
            int lin = tid + it * 128;
            int m = lin >> 3, kq = lin & 7;
            const float4 v = *reinterpret_cast<const float4*>(
                A + (long long)(m0 + m) * lda + k0 + kq * 4);
            uint4 w;
            w.x = f2tf32(v.x); w.y = f2tf32(v.y); w.z = f2tf32(v.z); w.w = f2tf32(v.w);
            *reinterpret_cast<uint4*>(&As[m * AS_LD + kq * 4]) = w;
        }
        if (BT) {
#pragma unroll
            for (int it = 0; it < 4; it++) {
                int lin = tid + it * 128;
                int n = lin >> 3, kq = lin & 7;
                const float4 v = *reinterpret_cast<const float4*>(
                    Bm + (long long)(n0 + n) * ldb + k0 + kq * 4);
                uint4 w;
                w.x = f2tf32(v.x); w.y = f2tf32(v.y); w.z = f2tf32(v.z); w.w = f2tf32(v.w);
                *reinterpret_cast<uint4*>(&Bs[n * AS_LD + kq * 4]) = w;
            }
        } else {
#pragma unroll
            for (int it = 0; it < 4; it++) {
                int lin = tid + it * 128;
                int k = lin >> 4, nq = lin & 15;
                int gn = n0 + nq * 4;
                if (((ldb & 3) == 0) && (gn + 3 < N)) {
                    const float4 v = *reinterpret_cast<const float4*>(
                        Bm + (long long)(k0 + k) * ldb + gn);
                    uint4 w;
                    w.x = f2tf32(v.x); w.y = f2tf32(v.y); w.z = f2tf32(v.z); w.w = f2tf32(v.w);
                    *reinterpret_cast<uint4*>(&Bs[k * BS_LD + nq * 4]) = w;
                } else {
#pragma unroll
                    for (int r = 0; r < 4; r++)
                        Bs[k * BS_LD + nq * 4 + r] =
                            (gn + r < N) ? f2tf32(Bm[(long long)(k0 + k) * ldb + gn + r]) : 0u;
                }
            }
        }
        __syncthreads();

#pragma unroll
        for (int kk = 0; kk < 4; kk++) {
            const int kb = kk * 8;
            unsigned aF[2][4], bF[4][2];
#pragma unroll
            for (int mt = 0; mt < 2; mt++) {
                int mr = wm + mt * 16 + g;
                aF[mt][0] = As[mr * AS_LD + kb + tig];
                aF[mt][1] = As[(mr + 8) * AS_LD + kb + tig];
                aF[mt][2] = As[mr * AS_LD + kb + tig + 4];
                aF[mt][3] = As[(mr + 8) * AS_LD + kb + tig + 4];
            }
#pragma unroll
            for (int nt = 0; nt < 4; nt++) {
                int nc = wn + nt * 8 + g;
                if (BT) {
                    bF[nt][0] = Bs[nc * AS_LD + kb + tig];
                    bF[nt][1] = Bs[nc * AS_LD + kb + tig + 4];
                } else {
                    bF[nt][0] = Bs[(kb + tig) * BS_LD + nc];
                    bF[nt][1] = Bs[(kb + tig + 4) * BS_LD + nc];
                }
            }
#pragma unroll
            for (int mt = 0; mt < 2; mt++)
#pragma unroll
                for (int nt = 0; nt < 4; nt++)
                    mma8(acc[mt][nt], aF[mt], bF[nt]);
        }
        __syncthreads();
    }

#pragma unroll
    for (int mt = 0; mt < 2; mt++) {
#pragma unroll
        for (int nt = 0; nt < 4; nt++) {
            int gm0 = m0 + wm + mt * 16 + g;
            int gn0 = n0 + wn + nt * 8 + tig * 2;
            float* c = acc[mt][nt];
#pragma unroll
            for (int e = 0; e < 4; e++) {
                int gm = gm0 + (e >> 1) * 8;
                int gn = gn0 + (e & 1);
                if (gn < N) {
                    float v = c[e] * alpha;
                    if (bias) v += bias[gn];
                    if (mul)  v *= mul[(long long)gm * ldc + gn];
                    C[(long long)gm * ldc + gn] = v;
                }
            }
        }
    }
}

// ---------------- depthwise conv over sequence dim ----------------
__global__ void dw_kernel(const float* __restrict__ Kin, const float* __restrict__ dw_w)
{
    long long idx = (long long)blockIdx.x * blockDim.x + threadIdx.x;
    if (idx >= (long long)BB * S * HID) return;
    int c  = (int)(idx % HID);
    long long bs = idx / HID;
    int s = (int)(bs % S);
    int b = (int)(bs / S);
    const float* kb = Kin + (long long)b * S * HID;
    float acc = 0.f;
#pragma unroll
    for (int t = 0; t < KS; t++) {
        int sp = s + t - PAD;
        if (sp >= 0 && sp < S) acc = fmaf(kb[(long long)sp * HID + c], dw_w[c * KS + t], acc);
    }
    g_dw[idx] = acc;
}

// ---------------- td softmax (row-independent) ----------------
__global__ void tdsm_kernel(const float* __restrict__ td, const int* __restrict__ mask)
{
    __shared__ float sred[8];
    const int b = blockIdx.x;
    const int t = threadIdx.x;            // 256 threads, 4 each
    const int lane = t & 31, wid = t >> 5;
    const int j0 = t * 4;
    const float* tr = td + b * S;
    const int* mr = mask + b * S;

    float v[4]; int am[4];
#pragma unroll
    for (int u = 0; u < 4; u++) { v[u] = tr[j0 + u]; am[u] = mr[j0 + u] != 0; }

    float ss = 0.f;
#pragma unroll
    for (int u = 0; u < 4; u++) ss += v[u] * v[u];
#pragma unroll
    for (int o = 16; o; o >>= 1) ss += __shfl_xor_sync(0xffffffffu, ss, o);
    if (lane == 0) sred[wid] = ss;
    __syncthreads();
    if (wid == 0) {
        float w = (lane < 8) ? sred[lane] : 0.f;
#pragma unroll
        for (int o = 4; o; o >>= 1) w += __shfl_xor_sync(0xffffffffu, w, o);
        if (lane == 0) sred[0] = w;
    }
    __syncthreads();
    float nrm = sqrtf(sred[0]);
    float inv = 1.f / fmaxf(nrm, 1e-12f);
    __syncthreads();

    float x[4];
#pragma unroll
    for (int u = 0; u < 4; u++) x[u] = am[u] ? v[u] * inv : -1e4f;

    float mx = fmaxf(fmaxf(x[0], x[1]), fmaxf(x[2], x[3]));
#pragma unroll
    for (int o = 16; o; o >>= 1) mx = fmaxf(mx, __shfl_xor_sync(0xffffffffu, mx, o));
    if (lane == 0) sred[wid] = mx;
    __syncthreads();
    if (wid == 0) {
        float w = (lane < 8) ? sred[lane] : -1e30f;
#pragma unroll
        for (int o = 4; o; o >>= 1) w = fmaxf(w, __shfl_xor_sync(0xffffffffu, w, o));
        if (lane == 0) sred[0] = w;
    }
    __syncthreads();
    mx = sred[0];
    __syncthreads();

    float e[4], le = 0.f;
#pragma unroll
    for (int u = 0; u < 4; u++) { e[u] = expf(x[u] - mx); le += e[u]; }
#pragma unroll
    for (int o = 16; o; o >>= 1) le += __shfl_xor_sync(0xffffffffu, le, o);
    if (lane == 0) sred[wid] = le;
    __syncthreads();
    if (wid == 0) {
        float w = (lane < 8) ? sred[lane] : 0.f;
#pragma unroll
        for (int o = 4; o; o >>= 1) w += __shfl_xor_sync(0xffffffffu, w, o);
        if (lane == 0) sred[0] = w;
    }
    __syncthreads();
    float dinv = 1.f / sred[0];
#pragma unroll
    for (int u = 0; u < 4; u++) g_tdsm[b * S + j0 + u] = e[u] * dinv;
}

// ---------------- fused per-row score pipeline ----------------
__device__ __forceinline__ float blockMax256(float v, float* sm, int lane, int wid)
{
#pragma unroll
    for (int o = 16; o; o >>= 1) v = fmaxf(v, __shfl_xor_sync(0xffffffffu, v, o));
    if (lane == 0) sm[wid] = v;
    __syncthreads();
    if (wid == 0) {
        float w = (lane < 8) ? sm[lane] : -3e38f;
#pragma unroll
        for (int o = 4; o; o >>= 1) w = fmaxf(w, __shfl_xor_sync(0xffffffffu, w, o));
        if (lane == 0) sm[0] = w;
    }
    __syncthreads();
    float r = sm[0];
    __syncthreads();
    return r;
}

__device__ __forceinline__ float blockSum256(float v, float* sm, int lane, int wid)
{
#pragma unroll
    for (int o = 16; o; o >>= 1) v += __shfl_xor_sync(0xffffffffu, v, o);
    if (lane == 0) sm[wid] = v;
    __syncthreads();
    if (wid == 0) {
        float w = (lane < 8) ? sm[lane] : 0.f;
#pragma unroll
        for (int o = 4; o; o >>= 1) w += __shfl_xor_sync(0xffffffffu, w, o);
        if (lane == 0) sm[0] = w;
    }
    __syncthreads();
    float r = sm[0];
    __syncthreads();
    return r;
}

__global__ void row_pipeline_kernel(const int* __restrict__ mask,
                                    const float* __restrict__ gammas)
{
    __shared__ float sred[8];
    __shared__ float swarp[8];
    const int t = threadIdx.x;
    const int lane = t & 31, wid = t >> 5;
    const int row = blockIdx.x;              // (b*H + h)*S + i
    const int i  = row & (S - 1);
    const int bh = row >> 10;
    const int h  = bh % H;
    const int b  = bh / H;
    float* srow = g_scores + (size_t)row * S;
    const int j0 = t * 4;

    float4 x4 = *reinterpret_cast<const float4*>(srow + j0);
    float x[4] = { x4.x, x4.y, x4.z, x4.w };
    const int* mr = mask + b * S;
    int am[4];
#pragma unroll
    for (int u = 0; u < 4; u++) am[u] = mr[j0 + u] != 0;
    float xm[4];
#pragma unroll
    for (int u = 0; u < 4; u++) xm[u] = am[u] ? x[u] : -1e8f;

    float mx = fmaxf(fmaxf(xm[0], xm[1]), fmaxf(xm[2], xm[3]));
    mx = blockMax256(mx, sred, lane, wid);
    float e[4], le = 0.f;
#pragma unroll
    for (int u = 0; u < 4; u++) { e[u] = expf(xm[u] - mx); le += e[u]; }
    float denom = blockSum256(le, sred, lane, wid);
    float inv = 1.f / denom;
    float p[4];
#pragma unroll
    for (int u = 0; u < 4; u++) p[u] = am[u] ? e[u] * inv : 0.f;

    float lp[4]; float run = 0.f;
#pragma unroll
    for (int u = 0; u < 4; u++) { run += p[u]; lp[u] = run; }
    float tot = run;
    float sc = tot;
#pragma unroll
    for (int o = 1; o < 32; o <<= 1) {
        float v = __shfl_up_sync(0xffffffffu, sc, o);
        if (lane >= o) sc += v;
    }
    if (lane == 31) swarp[wid] = sc;
    __syncthreads();
    if (wid == 0) {
        float v = (lane < 8) ? swarp[lane] : 0.f;
#pragma unroll
        for (int o = 1; o < 8; o <<= 1) {
            float w = __shfl_up_sync(0xffffffffu, v, o);
            if (lane >= o) v += w;
        }
        if (lane < 8) swarp[lane] = v;
    }
    __syncthreads();
    float off = ((wid > 0) ? swarp[wid - 1] : 0.f) + (sc - tot);
    float total = swarp[7];
    __syncthreads();

    const float g0 = gammas[h];
    const float gamma = -(g0 > 20.f ? g0 : log1pf(expf(g0)));
    const float* tdr = g_tdsm + b * S;

    float y[4];
#pragma unroll
    for (int u = 0; u < 4; u++) {
        int j = j0 + u;
        float cum = off + lp[u];
        float rem = total - cum;
        float pos = fabsf((float)(j - i));
        float ds = sqrtf(fmaxf(rem * pos, 0.f));
        float te = expf(ds * gamma);
        te = fminf(fmaxf(te, 1e-5f), 1e5f);
        float tef = te - ((j < i) ? tdr[j] : 0.f);
        y[u] = am[u] ? x[u] * tef : -1e8f;
    }

    float mx2 = fmaxf(fmaxf(y[0], y[1]), fmaxf(y[2], y[3]));
    mx2 = blockMax256(mx2, sred, lane, wid);
    float e2[4], le2 = 0.f;
#pragma unroll
    for (int u = 0; u < 4; u++) { e2[u] = expf(y[u] - mx2); le2 += e2[u]; }
    float denom2 = blockSum256(le2, sred, lane, wid);
    float inv2 = 1.f / denom2;
    float4 o4;
    o4.x = e2[0] * inv2; o4.y = e2[1] * inv2; o4.z = e2[2] * inv2; o4.w = e2[3] * inv2;
    *reinterpret_cast<float4*>(srow + j0) = o4;
}

// ---------------- dynamic span conv output (second half of d_out) ----------------
__global__ void convout_kernel(float* __restrict__ out)
{
    __shared__ float s_log[H * KS];
    __shared__ float s_ck[H * KS];
    const int bs = blockIdx.x;               // b*S + s
    const int b = bs >> 10, s = bs & (S - 1);
    const int t = threadIdx.x;               // 384
    if (t < H * KS) s_log[t] = g_ck[(size_t)bs * (H * KS) + t];
    __syncthreads();
    if (t < H) {
        float mx = -3e38f;
#pragma unroll
        for (int k = 0; k < KS; k++) mx = fmaxf(mx, s_log[t * KS + k]);
        float sum = 0.f, ev[KS];
#pragma unroll
        for (int k = 0; k < KS; k++) { ev[k] = expf(s_log[t * KS + k] - mx); sum += ev[k]; }
        float inv = 1.f / sum;
#pragma unroll
        for (int k = 0; k < KS; k++) s_ck[t * KS + k] = ev[k] * inv;
    }
    __syncthreads();
    const int h = t >> 6;
    float acc = 0.f;
#pragma unroll
    for (int k = 0; k < KS; k++) {
        int sp = s + k - PAD;
        if (sp >= 0 && sp < S)
            acc = fmaf(s_ck[h * KS + k], g_co[((size_t)b * S + sp) * AH + t], acc);
    }
    out[((size_t)b * S + s) * OUT_W + AH + t] = acc;
}

// ---------------- launcher ----------------
extern "C" void kernel_launch(void* const* d_in, const int* in_sizes, int n_in,
                              void* d_out, int out_size)
{
    const float* Q    = (const float*)d_in[0];
    const float* Kin  = (const float*)d_in[1];
    const float* V    = (const float*)d_in[2];
    const float* td   = (const float*)d_in[3];
    const int*   mask = (const int*)  d_in[4];
    const float* Wq   = (const float*)d_in[5];
    const float* Wk   = (const float*)d_in[6];
    const float* Wv   = (const float*)d_in[7];
    const float* dw_w = (const float*)d_in[8];
    const float* pw_w = (const float*)d_in[9];
    const float* sep_b= (const float*)d_in[10];
    const float* ck_W = (const float*)d_in[11];
    const float* ck_b = (const float*)d_in[12];
    const float* co_W = (const float*)d_in[13];
    const float* co_b = (const float*)d_in[14];
    const float* gammas=(const float*)d_in[15];
    float* out = (float*)d_out;

    float *p_scores, *p_mq, *p_mk, *p_mv, *p_co, *p_ca, *p_dw, *p_ck;
    cudaGetSymbolAddress((void**)&p_scores, g_scores);
    cudaGetSymbolAddress((void**)&p_mq, g_mq);
    cudaGetSymbolAddress((void**)&p_mk, g_mk);
    cudaGetSymbolAddress((void**)&p_mv, g_mv);
    cudaGetSymbolAddress((void**)&p_co, g_co);
    cudaGetSymbolAddress((void**)&p_ca, g_convattn);
    cudaGetSymbolAddress((void**)&p_dw, g_dw);
    cudaGetSymbolAddress((void**)&p_ck, g_ck);

    cudaFuncSetAttribute(tf32_gemm_pipe<true>,  cudaFuncAttributeMaxDynamicSharedMemorySize, PIPE_SMEM);
    cudaFuncSetAttribute(tf32_gemm_pipe<false>, cudaFuncAttributeMaxDynamicSharedMemorySize, PIPE_SMEM);
    cudaFuncSetAttribute(tf32_proj4,            cudaFuncAttributeMaxDynamicSharedMemorySize, PIPE_SMEM);

    const int M = BB * S;   // 4096

    // ---- 4 projections in ONE launch (z = op) ----
    Proj4 pr;
    pr.A[0] = Q;   pr.B[0] = Wq;   pr.bias[0] = nullptr; pr.C[0] = p_mq;
    pr.A[1] = Kin; pr.B[1] = Wk;   pr.bias[1] = nullptr; pr.C[1] = p_mk;
    pr.A[2] = V;   pr.B[2] = Wv;   pr.bias[2] = nullptr; pr.C[2] = p_mv;
    pr.A[3] = V;   pr.B[3] = co_W; pr.bias[3] = co_b;    pr.C[3] = p_co;
    tf32_proj4<<<dim3(AH / 64, M / 128, 4), 256, PIPE_SMEM>>>(pr, AH, HID, HID, AH, AH);

    // separable conv: depthwise then pointwise (fused with *mq -> conv_attn)
    {
        long long n = (long long)BB * S * HID;
        dw_kernel<<<(unsigned)((n + 255) / 256), 256>>>(Kin, dw_w);
    }
    tf32_gemm_pipe<true><<<dim3(AH / 64, M / 128, 1), 256, PIPE_SMEM>>>(
        p_dw, pw_w, sep_b, p_mq, p_ca,
        AH, HID, HID, HID, AH, 0, 0, 0, 0, 0, 0, 1, 1.f);

    // conv kernel layer (tiny, misaligned N=54): legacy checked kernel
    tf32_gemm<false><<<dim3((H * KS + 63) / 64, M / 64, 1), 128>>>(
        p_ca, ck_W, ck_b, nullptr, p_ck,
        M, H * KS, AH, AH, H * KS, H * KS, 0, 0, 0, 0, 0, 0, 1, 1.f);
    convout_kernel<<<BB * S, AH>>>(out);

    // td softmax (row-independent)
    tdsm_kernel<<<BB, 256>>>(td, mask);

    // attention scores (batched over b,h)
    tf32_gemm_pipe<true><<<dim3(S / 64, S / 128, BB * H), 256, PIPE_SMEM>>>(
        p_mq, p_mk, nullptr, nullptr, p_scores,
        S, D, AH, AH, S,
        (long long)S * AH, (long long)D,
        (long long)S * AH, (long long)D,
        (long long)H * S * S, (long long)S * S,
        H, 0.125f);

    // fused dist_func + double softmax, in place
    row_pipeline_kernel<<<BB * H * S, 256>>>(mask, gammas);

    // ctx = probs @ v, written straight into first half of d_out
    tf32_gemm_pipe<false><<<dim3(D / 64, S / 128, BB * H), 256, PIPE_SMEM>>>(
        p_scores, p_mv, nullptr, nullptr, out,
        D, S, S, AH, OUT_W,
        (long long)H * S * S, (long long)S * S,
        (long long)S * AH, (long long)D,
        (long long)S * OUT_W, (long long)D,
        H, 1.f);
}

// round 6
// speedup vs baseline: 2.8575x; 1.0334x over previous
#include <cuda_runtime.h>
#include <cuda_bf16.h>
#include <math.h>

#define HID 768
#define NSPLITS 12
#define H 6
#define D 64
#define AH 384
#define KS 9
#define PAD 4
#define BB 4
#define S 1024
#define OUT_W 768
#define CKN 54      // H*KS
#define POSB 8      // positions per ckconv block

// ---------------- scratch (device globals; no allocation allowed) ----------------
__device__ float g_scores[(size_t)BB * H * S * S];     // reused for probs
__device__ float g_mq[(size_t)BB * S * AH];
__device__ float g_mk[(size_t)BB * S * AH];
__device__ float g_mv[(size_t)BB * S * AH];
__device__ float g_co[(size_t)BB * S * AH];
__device__ float g_convattn[(size_t)BB * S * AH];      // mkc (pw output, pre-multiply)
__device__ float g_dw[(size_t)BB * S * HID];
__device__ float g_tdsm[(size_t)BB * S];

// ---------------- common helpers ----------------
__device__ __forceinline__ unsigned f2tf32(float x) {
    unsigned y;
    asm("cvt.rna.tf32.f32 %0, %1;" : "=r"(y) : "f"(x));
    return y;
}

__device__ __forceinline__ void mma8(float* c, const unsigned* a, const unsigned* b) {
    asm volatile("mma.sync.aligned.m16n8k8.row.col.f32.tf32.tf32.f32 "
        "{%0,%1,%2,%3},{%4,%5,%6,%7},{%8,%9},{%0,%1,%2,%3};"
        : "+f"(c[0]), "+f"(c[1]), "+f"(c[2]), "+f"(c[3])
        : "r"(a[0]), "r"(a[1]), "r"(a[2]), "r"(a[3]), "r"(b[0]), "r"(b[1]));
}

__device__ __forceinline__ unsigned smem_u32(const void* p) {
    return (unsigned)__cvta_generic_to_shared(p);
}
#define CP16(dst, src) asm volatile("cp.async.ca.shared.global [%0], [%1], 16;" :: "r"(dst), "l"(src))
#define CPCOMMIT()     asm volatile("cp.async.commit_group;")
#define CPWAIT(n)      asm volatile("cp.async.wait_group %0;" :: "n"(n))

// ================= pipelined TF32 GEMM (full-tile fast path) =================
// Requirements: M % 128 == 0, N % 64 == 0, K % 32 == 0, rows 16B-aligned.
// 256 threads, BM=128, BN=64, BK=32. C = alpha*A@B(^T) (+bias[n]) (*mul[m,n]).
#define PAS_LD 36
#define PBS_LDT 36   // BT: [n][k]
#define PBS_LDN 72   // !BT: [k][n]
#define PA_STG (128 * PAS_LD)
#define PB_STG (64 * PBS_LDT)
#define PIPE_SMEM ((2 * PA_STG + 2 * PB_STG) * 4)  // 55296 B

template<bool BT>
__device__ __forceinline__ void gemm_core_pipe(
    const float* __restrict__ A, const float* __restrict__ Bm,
    const float* __restrict__ bias, const float* __restrict__ mul,
    float* __restrict__ C, int N, int K, int lda, int ldb, int ldc, float alpha)
{
    extern __shared__ float dyn[];
    float* sA = dyn;
    float* sB = dyn + 2 * PA_STG;

    const int tid  = threadIdx.x;
    const int warp = tid >> 5, lane = tid & 31;
    const int g    = lane >> 2, tig = lane & 3;
    const int wm   = (warp >> 1) * 32, wn = (warp & 1) * 32;
    const int m0   = blockIdx.y * 128;
    const int n0   = blockIdx.x * 64;

    float acc[2][4][4];
#pragma unroll
    for (int mt = 0; mt < 2; mt++)
#pragma unroll
        for (int nt = 0; nt < 4; nt++)
#pragma unroll
            for (int e = 0; e < 4; e++) acc[mt][nt][e] = 0.f;

    const int nk = K >> 5;

    auto loadStage = [&](int ki, int st) {
        const int kbase = ki * 32;
#pragma unroll
        for (int it = 0; it < 4; it++) {
            int lin = tid + it * 256;
            int m = lin >> 3, kq = lin & 7;
            unsigned dst = smem_u32(&sA[st * PA_STG + m * PAS_LD + kq * 4]);
            const float* src = A + (long long)(m0 + m) * lda + kbase + kq * 4;
            CP16(dst, src);
        }
        if (BT) {
#pragma unroll
            for (int it = 0; it < 2; it++) {
                int lin = tid + it * 256;
                int n = lin >> 3, kq = lin & 7;
                unsigned dst = smem_u32(&sB[st * PB_STG + n * PBS_LDT + kq * 4]);
                const float* src = Bm + (long long)(n0 + n) * ldb + kbase + kq * 4;
                CP16(dst, src);
            }
        } else {
#pragma unroll
            for (int it = 0; it < 2; it++) {
                int lin = tid + it * 256;
                int k = lin >> 4, nq = lin & 15;
                unsigned dst = smem_u32(&sB[st * PB_STG + k * PBS_LDN + nq * 4]);
                const float* src = Bm + (long long)(kbase + k) * ldb + n0 + nq * 4;
                CP16(dst, src);
            }
        }
        CPCOMMIT();
    };

    loadStage(0, 0);
    for (int i = 0; i < nk; i++) {
        if (i + 1 < nk) { loadStage(i + 1, (i + 1) & 1); CPWAIT(1); }
        else            { CPWAIT(0); }
        __syncthreads();

        const float* as = &sA[(i & 1) * PA_STG];
        const float* bs = &sB[(i & 1) * PB_STG];
#pragma unroll
        for (int kk = 0; kk < 4; kk++) {
            const int kb = kk * 8;
            unsigned aF[2][4], bF[4][2];
#pragma unroll
            for (int mt = 0; mt < 2; mt++) {
                int mr = wm + mt * 16 + g;
                aF[mt][0] = f2tf32(as[mr * PAS_LD + kb + tig]);
                aF[mt][1] = f2tf32(as[(mr + 8) * PAS_LD + kb + tig]);
                aF[mt][2] = f2tf32(as[mr * PAS_LD + kb + tig + 4]);
                aF[mt][3] = f2tf32(as[(mr + 8) * PAS_LD + kb + tig + 4]);
            }
#pragma unroll
            for (int nt = 0; nt < 4; nt++) {
                int nc = wn + nt * 8 + g;
                if (BT) {
                    bF[nt][0] = f2tf32(bs[nc * PBS_LDT + kb + tig]);
                    bF[nt][1] = f2tf32(bs[nc * PBS_LDT + kb + tig + 4]);
                } else {
                    bF[nt][0] = f2tf32(bs[(kb + tig) * PBS_LDN + nc]);
                    bF[nt][1] = f2tf32(bs[(kb + tig + 4) * PBS_LDN + nc]);
                }
            }
#pragma unroll
            for (int mt = 0; mt < 2; mt++)
#pragma unroll
                for (int nt = 0; nt < 4; nt++)
                    mma8(acc[mt][nt], aF[mt], bF[nt]);
        }
        __syncthreads();
    }

#pragma unroll
    for (int mt = 0; mt < 2; mt++) {
#pragma unroll
        for (int nt = 0; nt < 4; nt++) {
            int gm0 = m0 + wm + mt * 16 + g;
            int gn0 = n0 + wn + nt * 8 + tig * 2;
            float* c = acc[mt][nt];
#pragma unroll
            for (int e = 0; e < 4; e++) {
                int gm = gm0 + (e >> 1) * 8;
                int gn = gn0 + (e & 1);
                float v = c[e] * alpha;
                if (bias) v += bias[gn];
                if (mul)  v *= mul[(long long)gm * ldc + gn];
                C[(long long)gm * ldc + gn] = v;
            }
        }
    }
}

template<bool BT>
__global__ __launch_bounds__(256) void tf32_gemm_pipe(
    const float* __restrict__ A, const float* __restrict__ Bm,
    const float* __restrict__ bias, const float* __restrict__ mul,
    float* __restrict__ C,
    int N, int K, int lda, int ldb, int ldc,
    long long sA1, long long sA2, long long sB1, long long sB2,
    long long sC1, long long sC2, int zdiv, float alpha)
{
    int z = blockIdx.z;
    int zb = z / zdiv, zh = z % zdiv;
    gemm_core_pipe<BT>(A + zb * sA1 + zh * sA2, Bm + zb * sB1 + zh * sB2,
                       bias, mul, C + zb * sC1 + zh * sC2,
                       N, K, lda, ldb, ldc, alpha);
}

// ---- 5 projections (Q,K,V,co,pw) in a single launch; per-op transpose flag ----
struct Proj5 {
    const float* A[5];
    const float* B[5];
    const float* bias[5];
    float* C[5];
    int bt[5];
    int ldb[5];
};

__global__ __launch_bounds__(256) void tf32_proj5(Proj5 p)
{
    int op = blockIdx.z;
    if (p.bt[op])
        gemm_core_pipe<true>(p.A[op], p.B[op], p.bias[op], nullptr, p.C[op],
                             AH, HID, HID, p.ldb[op], AH, 1.f);
    else
        gemm_core_pipe<false>(p.A[op], p.B[op], p.bias[op], nullptr, p.C[op],
                              AH, HID, HID, p.ldb[op], AH, 1.f);
}

// ================= fused ck GEMM + softmax + dynamic-span conv =================
// One block handles POSB consecutive positions (one warp each).
// conv_attn row = mkc * mq computed on the fly; 54 logits via fp32 dots from smem;
// per-head softmax; then the 9-tap dynamic conv over g_co -> out[:, AH:2AH].
#define CKCONV_SMEM ((AH * CKN + POSB * AH + POSB * 64) * 4)   // 97280 B

__global__ __launch_bounds__(256) void ckconv_kernel(
    const float* __restrict__ ckW, const float* __restrict__ ckb,
    float* __restrict__ out)
{
    extern __shared__ float sm[];
    float* sW   = sm;                       // [AH][CKN]
    float* sRow = sW + AH * CKN;            // [POSB][AH]
    float* sCk  = sRow + POSB * AH;         // [POSB][64]

    const int tid = threadIdx.x;
    const int warp = tid >> 5, lane = tid & 31;
    const int bs0 = blockIdx.x * POSB;

    // stage ck_W (coalesced)
    for (int i = tid; i < AH * CKN; i += 256) sW[i] = ckW[i];
    // stage conv_attn rows = mkc * mq (float4)
    for (int i = tid * 4; i < POSB * AH; i += 1024) {
        int p = i / AH, c = i % AH;
        size_t off = (size_t)(bs0 + p) * AH + c;
        float4 a = *reinterpret_cast<const float4*>(&g_convattn[off]);
        float4 b = *reinterpret_cast<const float4*>(&g_mq[off]);
        float4 r;
        r.x = a.x * b.x; r.y = a.y * b.y; r.z = a.z * b.z; r.w = a.w * b.w;
        *reinterpret_cast<float4*>(&sRow[p * AH + c]) = r;
    }
    __syncthreads();

    const int p  = warp;
    const int bs = bs0 + p;
    const int b  = bs >> 10, s = bs & (S - 1);
    const float* row = &sRow[p * AH];

    // 54 logits per position (lane-consecutive W reads: conflict-free)
    for (int n = lane; n < CKN; n += 32) {
        float acc = ckb[n];
#pragma unroll 8
        for (int k = 0; k < AH; k++)
            acc = fmaf(row[k], sW[k * CKN + n], acc);
        sCk[p * 64 + n] = acc;
    }
    __syncwarp();

    // per-head softmax over KS=9
    if (lane < H) {
        float* l = &sCk[p * 64 + lane * KS];
        float mx = -3e38f;
#pragma unroll
        for (int k = 0; k < KS; k++) mx = fmaxf(mx, l[k]);
        float ev[KS], sum = 0.f;
#pragma unroll
        for (int k = 0; k < KS; k++) { ev[k] = expf(l[k] - mx); sum += ev[k]; }
        float inv = 1.f / sum;
#pragma unroll
        for (int k = 0; k < KS; k++) l[k] = ev[k] * inv;
    }
    __syncwarp();

    // dynamic conv output
    for (int c = lane; c < AH; c += 32) {
        int h = c >> 6;
        float acc = 0.f;
#pragma unroll
        for (int k = 0; k < KS; k++) {
            int sp = s + k - PAD;
            if (sp >= 0 && sp < S)
                acc = fmaf(sCk[p * 64 + h * KS + k],
                           g_co[((size_t)b * S + sp) * AH + c], acc);
        }
        out[((size_t)b * S + s) * OUT_W + AH + c] = acc;
    }
}

// ---------------- depthwise conv over sequence dim ----------------
__global__ void dw_kernel(const float* __restrict__ Kin, const float* __restrict__ dw_w)
{
    long long idx = (long long)blockIdx.x * blockDim.x + threadIdx.x;
    if (idx >= (long long)BB * S * HID) return;
    int c  = (int)(idx % HID);
    long long bs = idx / HID;
    int s = (int)(bs % S);
    int b = (int)(bs / S);
    const float* kb = Kin + (long long)b * S * HID;
    float acc = 0.f;
#pragma unroll
    for (int t = 0; t < KS; t++) {
        int sp = s + t - PAD;
        if (sp >= 0 && sp < S) acc = fmaf(kb[(long long)sp * HID + c], dw_w[c * KS + t], acc);
    }
    g_dw[idx] = acc;
}

// ---------------- td softmax (row-independent) ----------------
__global__ void tdsm_kernel(const float* __restrict__ td, const int* __restrict__ mask)
{
    __shared__ float sred[8];
    const int b = blockIdx.x;
    const int t = threadIdx.x;
    const int lane = t & 31, wid = t >> 5;
    const int j0 = t * 4;
    const float* tr = td + b * S;
    const int* mr = mask + b * S;

    float v[4]; int am[4];
#pragma unroll
    for (int u = 0; u < 4; u++) { v[u] = tr[j0 + u]; am[u] = mr[j0 + u] != 0; }

    float ss = 0.f;
#pragma unroll
    for (int u = 0; u < 4; u++) ss += v[u] * v[u];
#pragma unroll
    for (int o = 16; o; o >>= 1) ss += __shfl_xor_sync(0xffffffffu, ss, o);
    if (lane == 0) sred[wid] = ss;
    __syncthreads();
    if (wid == 0) {
        float w = (lane < 8) ? sred[lane] : 0.f;
#pragma unroll
        for (int o = 4; o; o >>= 1) w += __shfl_xor_sync(0xffffffffu, w, o);
        if (lane == 0) sred[0] = w;
    }
    __syncthreads();
    float nrm = sqrtf(sred[0]);
    float inv = 1.f / fmaxf(nrm, 1e-12f);
    __syncthreads();

    float x[4];
#pragma unroll
    for (int u = 0; u < 4; u++) x[u] = am[u] ? v[u] * inv : -1e4f;

    float mx = fmaxf(fmaxf(x[0], x[1]), fmaxf(x[2], x[3]));
#pragma unroll
    for (int o = 16; o; o >>= 1) mx = fmaxf(mx, __shfl_xor_sync(0xffffffffu, mx, o));
    if (lane == 0) sred[wid] = mx;
    __syncthreads();
    if (wid == 0) {
        float w = (lane < 8) ? sred[lane] : -1e30f;
#pragma unroll
        for (int o = 4; o; o >>= 1) w = fmaxf(w, __shfl_xor_sync(0xffffffffu, w, o));
        if (lane == 0) sred[0] = w;
    }
    __syncthreads();
    mx = sred[0];
    __syncthreads();

    float e[4], le = 0.f;
#pragma unroll
    for (int u = 0; u < 4; u++) { e[u] = expf(x[u] - mx); le += e[u]; }
#pragma unroll
    for (int o = 16; o; o >>= 1) le += __shfl_xor_sync(0xffffffffu, le, o);
    if (lane == 0) sred[wid] = le;
    __syncthreads();
    if (wid == 0) {
        float w = (lane < 8) ? sred[lane] : 0.f;
#pragma unroll
        for (int o = 4; o; o >>= 1) w += __shfl_xor_sync(0xffffffffu, w, o);
        if (lane == 0) sred[0] = w;
    }
    __syncthreads();
    float dinv = 1.f / sred[0];
#pragma unroll
    for (int u = 0; u < 4; u++) g_tdsm[b * S + j0 + u] = e[u] * dinv;
}

// ---------------- fused per-row score pipeline ----------------
__device__ __forceinline__ float blockMax256(float v, float* sm, int lane, int wid)
{
#pragma unroll
    for (int o = 16; o; o >>= 1) v = fmaxf(v, __shfl_xor_sync(0xffffffffu, v, o));
    if (lane == 0) sm[wid] = v;
    __syncthreads();
    if (wid == 0) {
        float w = (lane < 8) ? sm[lane] : -3e38f;
#pragma unroll
        for (int o = 4; o; o >>= 1) w = fmaxf(w, __shfl_xor_sync(0xffffffffu, w, o));
        if (lane == 0) sm[0] = w;
    }
    __syncthreads();
    float r = sm[0];
    __syncthreads();
    return r;
}

__device__ __forceinline__ float blockSum256(float v, float* sm, int lane, int wid)
{
#pragma unroll
    for (int o = 16; o; o >>= 1) v += __shfl_xor_sync(0xffffffffu, v, o);
    if (lane == 0) sm[wid] = v;
    __syncthreads();
    if (wid == 0) {
        float w = (lane < 8) ? sm[lane] : 0.f;
#pragma unroll
        for (int o = 4; o; o >>= 1) w += __shfl_xor_sync(0xffffffffu, w, o);
        if (lane == 0) sm[0] = w;
    }
    __syncthreads();
    float r = sm[0];
    __syncthreads();
    return r;
}

__global__ void row_pipeline_kernel(const int* __restrict__ mask,
                                    const float* __restrict__ gammas)
{
    __shared__ float sred[8];
    __shared__ float swarp[8];
    const int t = threadIdx.x;
    const int lane = t & 31, wid = t >> 5;
    const int row = blockIdx.x;              // (b*H + h)*S + i
    const int i  = row & (S - 1);
    const int bh = row >> 10;
    const int h  = bh % H;
    const int b  = bh / H;
    float* srow = g_scores + (size_t)row * S;
    const int j0 = t * 4;

    float4 x4 = *reinterpret_cast<const float4*>(srow + j0);
    float x[4] = { x4.x, x4.y, x4.z, x4.w };
    const int* mr = mask + b * S;
    int am[4];
#pragma unroll
    for (int u = 0; u < 4; u++) am[u] = mr[j0 + u] != 0;
    float xm[4];
#pragma unroll
    for (int u = 0; u < 4; u++) xm[u] = am[u] ? x[u] : -1e8f;

    float mx = fmaxf(fmaxf(xm[0], xm[1]), fmaxf(xm[2], xm[3]));
    mx = blockMax256(mx, sred, lane, wid);
    float e[4], le = 0.f;
#pragma unroll
    for (int u = 0; u < 4; u++) { e[u] = expf(xm[u] - mx); le += e[u]; }
    float denom = blockSum256(le, sred, lane, wid);
    float inv = 1.f / denom;
    float p[4];
#pragma unroll
    for (int u = 0; u < 4; u++) p[u] = am[u] ? e[u] * inv : 0.f;

    float lp[4]; float run = 0.f;
#pragma unroll
    for (int u = 0; u < 4; u++) { run += p[u]; lp[u] = run; }
    float tot = run;
    float sc = tot;
#pragma unroll
    for (int o = 1; o < 32; o <<= 1) {
        float v = __shfl_up_sync(0xffffffffu, sc, o);
        if (lane >= o) sc += v;
    }
    if (lane == 31) swarp[wid] = sc;
    __syncthreads();
    if (wid == 0) {
        float v = (lane < 8) ? swarp[lane] : 0.f;
#pragma unroll
        for (int o = 1; o < 8; o <<= 1) {
            float w = __shfl_up_sync(0xffffffffu, v, o);
            if (lane >= o) v += w;
        }
        if (lane < 8) swarp[lane] = v;
    }
    __syncthreads();
    float off = ((wid > 0) ? swarp[wid - 1] : 0.f) + (sc - tot);
    float total = swarp[7];
    __syncthreads();

    const float g0 = gammas[h];
    const float gamma = -(g0 > 20.f ? g0 : log1pf(expf(g0)));
    const float* tdr = g_tdsm + b * S;

    float y[4];
#pragma unroll
    for (int u = 0; u < 4; u++) {
        int j = j0 + u;
        float cum = off + lp[u];
        float rem = total - cum;
        float pos = fabsf((float)(j - i));
        float ds = sqrtf(fmaxf(rem * pos, 0.f));
        float te = expf(ds * gamma);
        te = fminf(fmaxf(te, 1e-5f), 1e5f);
        float tef = te - ((j < i) ? tdr[j] : 0.f);
        y[u] = am[u] ? x[u] * tef : -1e8f;
    }

    float mx2 = fmaxf(fmaxf(y[0], y[1]), fmaxf(y[2], y[3]));
    mx2 = blockMax256(mx2, sred, lane, wid);
    float e2[4], le2 = 0.f;
#pragma unroll
    for (int u = 0; u < 4; u++) { e2[u] = expf(y[u] - mx2); le2 += e2[u]; }
    float denom2 = blockSum256(le2, sred, lane, wid);
    float inv2 = 1.f / denom2;
    float4 o4;
    o4.x = e2[0] * inv2; o4.y = e2[1] * inv2; o4.z = e2[2] * inv2; o4.w = e2[3] * inv2;
    *reinterpret_cast<float4*>(srow + j0) = o4;
}

// ---------------- launcher ----------------
extern "C" void kernel_launch(void* const* d_in, const int* in_sizes, int n_in,
                              void* d_out, int out_size)
{
    const float* Q    = (const float*)d_in[0];
    const float* Kin  = (const float*)d_in[1];
    const float* V    = (const float*)d_in[2];
    const float* td   = (const float*)d_in[3];
    const int*   mask = (const int*)  d_in[4];
    const float* Wq   = (const float*)d_in[5];
    const float* Wk   = (const float*)d_in[6];
    const float* Wv   = (const float*)d_in[7];
    const float* dw_w = (const float*)d_in[8];
    const float* pw_w = (const float*)d_in[9];
    const float* sep_b= (const float*)d_in[10];
    const float* ck_W = (const float*)d_in[11];
    const float* ck_b = (const float*)d_in[12];
    const float* co_W = (const float*)d_in[13];
    const float* co_b = (const float*)d_in[14];
    const float* gammas=(const float*)d_in[15];
    float* out = (float*)d_out;

    float *p_scores, *p_mq, *p_mk, *p_mv, *p_co, *p_ca, *p_dw;
    cudaGetSymbolAddress((void**)&p_scores, g_scores);
    cudaGetSymbolAddress((void**)&p_mq, g_mq);
    cudaGetSymbolAddress((void**)&p_mk, g_mk);
    cudaGetSymbolAddress((void**)&p_mv, g_mv);
    cudaGetSymbolAddress((void**)&p_co, g_co);
    cudaGetSymbolAddress((void**)&p_ca, g_convattn);
    cudaGetSymbolAddress((void**)&p_dw, g_dw);

    cudaFuncSetAttribute(tf32_gemm_pipe<true>,  cudaFuncAttributeMaxDynamicSharedMemorySize, PIPE_SMEM);
    cudaFuncSetAttribute(tf32_gemm_pipe<false>, cudaFuncAttributeMaxDynamicSharedMemorySize, PIPE_SMEM);
    cudaFuncSetAttribute(tf32_proj5,            cudaFuncAttributeMaxDynamicSharedMemorySize, PIPE_SMEM);
    cudaFuncSetAttribute(ckconv_kernel,         cudaFuncAttributeMaxDynamicSharedMemorySize, CKCONV_SMEM);

    const int M = BB * S;   // 4096

    // td softmax (independent of everything else)
    tdsm_kernel<<<BB, 256>>>(td, mask);

    // depthwise conv (feeds pw op in proj5)
    {
        long long n = (long long)BB * S * HID;
        dw_kernel<<<(unsigned)((n + 255) / 256), 256>>>(Kin, dw_w);
    }

    // ---- 5 projections in ONE launch (z = op): Q, K, V, co, pw ----
    Proj5 pr;
    pr.A[0] = Q;    pr.B[0] = Wq;   pr.bias[0] = nullptr; pr.C[0] = p_mq; pr.bt[0] = 0; pr.ldb[0] = AH;
    pr.A[1] = Kin;  pr.B[1] = Wk;   pr.bias[1] = nullptr; pr.C[1] = p_mk; pr.bt[1] = 0; pr.ldb[1] = AH;
    pr.A[2] = V;    pr.B[2] = Wv;   pr.bias[2] = nullptr; pr.C[2] = p_mv; pr.bt[2] = 0; pr.ldb[2] = AH;
    pr.A[3] = V;    pr.B[3] = co_W; pr.bias[3] = co_b;    pr.C[3] = p_co; pr.bt[3] = 0; pr.ldb[3] = AH;
    pr.A[4] = p_dw; pr.B[4] = pw_w; pr.bias[4] = sep_b;   pr.C[4] = p_ca; pr.bt[4] = 1; pr.ldb[4] = HID;
    tf32_proj5<<<dim3(AH / 64, M / 128, 5), 256, PIPE_SMEM>>>(pr);

    // fused ck GEMM + softmax + dynamic conv -> out[:, AH:2AH]
    ckconv_kernel<<<M / POSB, 256, CKCONV_SMEM>>>(ck_W, ck_b, out);

    // attention scores (batched over b,h)
    tf32_gemm_pipe<true><<<dim3(S / 64, S / 128, BB * H), 256, PIPE_SMEM>>>(
        p_mq, p_mk, nullptr, nullptr, p_scores,
        S, D, AH, AH, S,
        (long long)S * AH, (long long)D,
        (long long)S * AH, (long long)D,
        (long long)H * S * S, (long long)S * S,
        H, 0.125f);

    // fused dist_func + double softmax, in place
    row_pipeline_kernel<<<BB * H * S, 256>>>(mask, gammas);

    // ctx = probs @ v, written straight into first half of d_out
    tf32_gemm_pipe<false><<<dim3(D / 64, S / 128, BB * H), 256, PIPE_SMEM>>>(
        p_scores, p_mv, nullptr, nullptr, out,
        D, S, S, AH, OUT_W,
        (long long)H * S * S, (long long)S * S,
        (long long)S * AH, (long long)D,
        (long long)S * OUT_W, (long long)D,
        H, 1.f);
}

// round 7
// speedup vs baseline: 3.0381x; 1.0632x over previous
#include <cuda_runtime.h>
#include <cuda_bf16.h>
#include <math.h>

#define HID 768
#define NSPLITS 12
#define H 6
#define D 64
#define AH 384
#define KS 9
#define PAD 4
#define BB 4
#define S 1024
#define OUT_W 768
#define CKN 54      // H*KS

// ---------------- scratch (device globals; no allocation allowed) ----------------
__device__ float g_scores[(size_t)BB * H * S * S];     // reused for probs
__device__ float g_mq[(size_t)BB * S * AH];
__device__ float g_mk[(size_t)BB * S * AH];
__device__ float g_mv[(size_t)BB * S * AH];
__device__ float g_co[(size_t)BB * S * AH];
__device__ float g_convattn[(size_t)BB * S * AH];      // mkc, then *= mq in place
__device__ float g_dw[(size_t)BB * S * HID];
__device__ float g_tdsm[(size_t)BB * S];
__device__ float g_ck[(size_t)BB * S * 64];            // padded ck logits
__device__ float g_ckWp[(size_t)AH * 64];              // padded ck_W

// ---------------- common helpers ----------------
__device__ __forceinline__ unsigned f2tf32(float x) {
    unsigned y;
    asm("cvt.rna.tf32.f32 %0, %1;" : "=r"(y) : "f"(x));
    return y;
}

__device__ __forceinline__ void mma8(float* c, const unsigned* a, const unsigned* b) {
    asm volatile("mma.sync.aligned.m16n8k8.row.col.f32.tf32.tf32.f32 "
        "{%0,%1,%2,%3},{%4,%5,%6,%7},{%8,%9},{%0,%1,%2,%3};"
        : "+f"(c[0]), "+f"(c[1]), "+f"(c[2]), "+f"(c[3])
        : "r"(a[0]), "r"(a[1]), "r"(a[2]), "r"(a[3]), "r"(b[0]), "r"(b[1]));
}

__device__ __forceinline__ unsigned smem_u32(const void* p) {
    return (unsigned)__cvta_generic_to_shared(p);
}
#define CP16(dst, src) asm volatile("cp.async.ca.shared.global [%0], [%1], 16;" :: "r"(dst), "l"(src))
#define CPCOMMIT()     asm volatile("cp.async.commit_group;")
#define CPWAIT(n)      asm volatile("cp.async.wait_group %0;" :: "n"(n))

// ================= pipelined TF32 GEMM (full-tile fast path) =================
// Requirements: M % 128 == 0, N % 64 == 0, K % 32 == 0, rows 16B-aligned.
// 256 threads, BM=128, BN=64, BK=32. C = alpha*A@B(^T) (+bias[n]) (*mul[m,n]).
#define PAS_LD 36
#define PBS_LDT 36   // BT: [n][k]
#define PBS_LDN 72   // !BT: [k][n]
#define PA_STG (128 * PAS_LD)
#define PB_STG (64 * PBS_LDT)
#define PIPE_SMEM ((2 * PA_STG + 2 * PB_STG) * 4)  // 55296 B

template<bool BT>
__device__ __forceinline__ void gemm_core_pipe(
    const float* __restrict__ A, const float* __restrict__ Bm,
    const float* __restrict__ bias, const float* __restrict__ mul,
    float* __restrict__ C, int N, int K, int lda, int ldb, int ldc, float alpha)
{
    extern __shared__ float dyn[];
    float* sA = dyn;
    float* sB = dyn + 2 * PA_STG;

    const int tid  = threadIdx.x;
    const int warp = tid >> 5, lane = tid & 31;
    const int g    = lane >> 2, tig = lane & 3;
    const int wm   = (warp >> 1) * 32, wn = (warp & 1) * 32;
    const int m0   = blockIdx.y * 128;
    const int n0   = blockIdx.x * 64;

    float acc[2][4][4];
#pragma unroll
    for (int mt = 0; mt < 2; mt++)
#pragma unroll
        for (int nt = 0; nt < 4; nt++)
#pragma unroll
            for (int e = 0; e < 4; e++) acc[mt][nt][e] = 0.f;

    const int nk = K >> 5;

    auto loadStage = [&](int ki, int st) {
        const int kbase = ki * 32;
#pragma unroll
        for (int it = 0; it < 4; it++) {
            int lin = tid + it * 256;
            int m = lin >> 3, kq = lin & 7;
            unsigned dst = smem_u32(&sA[st * PA_STG + m * PAS_LD + kq * 4]);
            const float* src = A + (long long)(m0 + m) * lda + kbase + kq * 4;
            CP16(dst, src);
        }
        if (BT) {
#pragma unroll
            for (int it = 0; it < 2; it++) {
                int lin = tid + it * 256;
                int n = lin >> 3, kq = lin & 7;
                unsigned dst = smem_u32(&sB[st * PB_STG + n * PBS_LDT + kq * 4]);
                const float* src = Bm + (long long)(n0 + n) * ldb + kbase + kq * 4;
                CP16(dst, src);
            }
        } else {
#pragma unroll
            for (int it = 0; it < 2; it++) {
                int lin = tid + it * 256;
                int k = lin >> 4, nq = lin & 15;
                unsigned dst = smem_u32(&sB[st * PB_STG + k * PBS_LDN + nq * 4]);
                const float* src = Bm + (long long)(kbase + k) * ldb + n0 + nq * 4;
                CP16(dst, src);
            }
        }
        CPCOMMIT();
    };

    loadStage(0, 0);
    for (int i = 0; i < nk; i++) {
        if (i + 1 < nk) { loadStage(i + 1, (i + 1) & 1); CPWAIT(1); }
        else            { CPWAIT(0); }
        __syncthreads();

        const float* as = &sA[(i & 1) * PA_STG];
        const float* bs = &sB[(i & 1) * PB_STG];
#pragma unroll
        for (int kk = 0; kk < 4; kk++) {
            const int kb = kk * 8;
            unsigned aF[2][4], bF[4][2];
#pragma unroll
            for (int mt = 0; mt < 2; mt++) {
                int mr = wm + mt * 16 + g;
                aF[mt][0] = f2tf32(as[mr * PAS_LD + kb + tig]);
                aF[mt][1] = f2tf32(as[(mr + 8) * PAS_LD + kb + tig]);
                aF[mt][2] = f2tf32(as[mr * PAS_LD + kb + tig + 4]);
                aF[mt][3] = f2tf32(as[(mr + 8) * PAS_LD + kb + tig + 4]);
            }
#pragma unroll
            for (int nt = 0; nt < 4; nt++) {
                int nc = wn + nt * 8 + g;
                if (BT) {
                    bF[nt][0] = f2tf32(bs[nc * PBS_LDT + kb + tig]);
                    bF[nt][1] = f2tf32(bs[nc * PBS_LDT + kb + tig + 4]);
                } else {
                    bF[nt][0] = f2tf32(bs[(kb + tig) * PBS_LDN + nc]);
                    bF[nt][1] = f2tf32(bs[(kb + tig + 4) * PBS_LDN + nc]);
                }
            }
#pragma unroll
            for (int mt = 0; mt < 2; mt++)
#pragma unroll
                for (int nt = 0; nt < 4; nt++)
                    mma8(acc[mt][nt], aF[mt], bF[nt]);
        }
        __syncthreads();
    }

#pragma unroll
    for (int mt = 0; mt < 2; mt++) {
#pragma unroll
        for (int nt = 0; nt < 4; nt++) {
            int gm0 = m0 + wm + mt * 16 + g;
            int gn0 = n0 + wn + nt * 8 + tig * 2;
            float* c = acc[mt][nt];
#pragma unroll
            for (int e = 0; e < 4; e++) {
                int gm = gm0 + (e >> 1) * 8;
                int gn = gn0 + (e & 1);
                float v = c[e] * alpha;
                if (bias) v += bias[gn];
                if (mul)  v *= mul[(long long)gm * ldc + gn];
                C[(long long)gm * ldc + gn] = v;
            }
        }
    }
}

template<bool BT>
__global__ __launch_bounds__(256) void tf32_gemm_pipe(
    const float* __restrict__ A, const float* __restrict__ Bm,
    const float* __restrict__ bias, const float* __restrict__ mul,
    float* __restrict__ C,
    int N, int K, int lda, int ldb, int ldc,
    long long sA1, long long sA2, long long sB1, long long sB2,
    long long sC1, long long sC2, int zdiv, float alpha)
{
    int z = blockIdx.z;
    int zb = z / zdiv, zh = z % zdiv;
    gemm_core_pipe<BT>(A + zb * sA1 + zh * sA2, Bm + zb * sB1 + zh * sB2,
                       bias, mul, C + zb * sC1 + zh * sC2,
                       N, K, lda, ldb, ldc, alpha);
}

// ---- 5 projections (Q,K,V,co,pw) in a single launch; per-op transpose flag ----
struct Proj5 {
    const float* A[5];
    const float* B[5];
    const float* bias[5];
    float* C[5];
    int bt[5];
    int ldb[5];
};

__global__ __launch_bounds__(256) void tf32_proj5(Proj5 p)
{
    int op = blockIdx.z;
    if (p.bt[op])
        gemm_core_pipe<true>(p.A[op], p.B[op], p.bias[op], nullptr, p.C[op],
                             AH, HID, HID, p.ldb[op], AH, 1.f);
    else
        gemm_core_pipe<false>(p.A[op], p.B[op], p.bias[op], nullptr, p.C[op],
                              AH, HID, HID, p.ldb[op], AH, 1.f);
}

// ---------------- elementwise: g_convattn *= g_mq (float4) ----------------
__global__ void mul_kernel()
{
    long long i = ((long long)blockIdx.x * blockDim.x + threadIdx.x) * 4;
    if (i >= (long long)BB * S * AH) return;
    float4 a = *reinterpret_cast<const float4*>(&g_convattn[i]);
    float4 b = *reinterpret_cast<const float4*>(&g_mq[i]);
    a.x *= b.x; a.y *= b.y; a.z *= b.z; a.w *= b.w;
    *reinterpret_cast<float4*>(&g_convattn[i]) = a;
}

// ---------------- repack ck_W (384x54) -> g_ckWp (384x64, zero-padded) ----------------
__global__ void padW_kernel(const float* __restrict__ ckW)
{
    int i = blockIdx.x * blockDim.x + threadIdx.x;
    if (i >= AH * 64) return;
    int k = i >> 6, n = i & 63;
    g_ckWp[i] = (n < CKN) ? ckW[k * CKN + n] : 0.f;
}

// ---------------- dynamic span conv output (second half of d_out) ----------------
__global__ void convout_kernel(const float* __restrict__ ckb, float* __restrict__ out)
{
    __shared__ float s_ck[H * KS];
    const int bs = blockIdx.x;               // b*S + s
    const int b = bs >> 10, s = bs & (S - 1);
    const int t = threadIdx.x;               // 384
    __shared__ float s_log[H * KS];
    if (t < H * KS) s_log[t] = g_ck[(size_t)bs * 64 + t] + ckb[t];
    __syncthreads();
    if (t < H) {
        float mx = -3e38f;
#pragma unroll
        for (int k = 0; k < KS; k++) mx = fmaxf(mx, s_log[t * KS + k]);
        float sum = 0.f, ev[KS];
#pragma unroll
        for (int k = 0; k < KS; k++) { ev[k] = expf(s_log[t * KS + k] - mx); sum += ev[k]; }
        float inv = 1.f / sum;
#pragma unroll
        for (int k = 0; k < KS; k++) s_ck[t * KS + k] = ev[k] * inv;
    }
    __syncthreads();
    const int h = t >> 6;
    float acc = 0.f;
#pragma unroll
    for (int k = 0; k < KS; k++) {
        int sp = s + k - PAD;
        if (sp >= 0 && sp < S)
            acc = fmaf(s_ck[h * KS + k], g_co[((size_t)b * S + sp) * AH + t], acc);
    }
    out[((size_t)b * S + s) * OUT_W + AH + t] = acc;
}

// ---------------- depthwise conv over sequence dim ----------------
__global__ void dw_kernel(const float* __restrict__ Kin, const float* __restrict__ dw_w)
{
    long long idx = (long long)blockIdx.x * blockDim.x + threadIdx.x;
    if (idx >= (long long)BB * S * HID) return;
    int c  = (int)(idx % HID);
    long long bs = idx / HID;
    int s = (int)(bs % S);
    int b = (int)(bs / S);
    const float* kb = Kin + (long long)b * S * HID;
    float acc = 0.f;
#pragma unroll
    for (int t = 0; t < KS; t++) {
        int sp = s + t - PAD;
        if (sp >= 0 && sp < S) acc = fmaf(kb[(long long)sp * HID + c], dw_w[c * KS + t], acc);
    }
    g_dw[idx] = acc;
}

// ---------------- td softmax (row-independent) ----------------
__global__ void tdsm_kernel(const float* __restrict__ td, const int* __restrict__ mask)
{
    __shared__ float sred[8];
    const int b = blockIdx.x;
    const int t = threadIdx.x;
    const int lane = t & 31, wid = t >> 5;
    const int j0 = t * 4;
    const float* tr = td + b * S;
    const int* mr = mask + b * S;

    float v[4]; int am[4];
#pragma unroll
    for (int u = 0; u < 4; u++) { v[u] = tr[j0 + u]; am[u] = mr[j0 + u] != 0; }

    float ss = 0.f;
#pragma unroll
    for (int u = 0; u < 4; u++) ss += v[u] * v[u];
#pragma unroll
    for (int o = 16; o; o >>= 1) ss += __shfl_xor_sync(0xffffffffu, ss, o);
    if (lane == 0) sred[wid] = ss;
    __syncthreads();
    if (wid == 0) {
        float w = (lane < 8) ? sred[lane] : 0.f;
#pragma unroll
        for (int o = 4; o; o >>= 1) w += __shfl_xor_sync(0xffffffffu, w, o);
        if (lane == 0) sred[0] = w;
    }
    __syncthreads();
    float nrm = sqrtf(sred[0]);
    float inv = 1.f / fmaxf(nrm, 1e-12f);
    __syncthreads();

    float x[4];
#pragma unroll
    for (int u = 0; u < 4; u++) x[u] = am[u] ? v[u] * inv : -1e4f;

    float mx = fmaxf(fmaxf(x[0], x[1]), fmaxf(x[2], x[3]));
#pragma unroll
    for (int o = 16; o; o >>= 1) mx = fmaxf(mx, __shfl_xor_sync(0xffffffffu, mx, o));
    if (lane == 0) sred[wid] = mx;
    __syncthreads();
    if (wid == 0) {
        float w = (lane < 8) ? sred[lane] : -1e30f;
#pragma unroll
        for (int o = 4; o; o >>= 1) w = fmaxf(w, __shfl_xor_sync(0xffffffffu, w, o));
        if (lane == 0) sred[0] = w;
    }
    __syncthreads();
    mx = sred[0];
    __syncthreads();

    float e[4], le = 0.f;
#pragma unroll
    for (int u = 0; u < 4; u++) { e[u] = expf(x[u] - mx); le += e[u]; }
#pragma unroll
    for (int o = 16; o; o >>= 1) le += __shfl_xor_sync(0xffffffffu, le, o);
    if (lane == 0) sred[wid] = le;
    __syncthreads();
    if (wid == 0) {
        float w = (lane < 8) ? sred[lane] : 0.f;
#pragma unroll
        for (int o = 4; o; o >>= 1) w += __shfl_xor_sync(0xffffffffu, w, o);
        if (lane == 0) sred[0] = w;
    }
    __syncthreads();
    float dinv = 1.f / sred[0];
#pragma unroll
    for (int u = 0; u < 4; u++) g_tdsm[b * S + j0 + u] = e[u] * dinv;
}

// ---------------- fused per-row score pipeline ----------------
__device__ __forceinline__ float blockMax256(float v, float* sm, int lane, int wid)
{
#pragma unroll
    for (int o = 16; o; o >>= 1) v = fmaxf(v, __shfl_xor_sync(0xffffffffu, v, o));
    if (lane == 0) sm[wid] = v;
    __syncthreads();
    if (wid == 0) {
        float w = (lane < 8) ? sm[lane] : -3e38f;
#pragma unroll
        for (int o = 4; o; o >>= 1) w = fmaxf(w, __shfl_xor_sync(0xffffffffu, w, o));
        if (lane == 0) sm[0] = w;
    }
    __syncthreads();
    float r = sm[0];
    __syncthreads();
    return r;
}

__device__ __forceinline__ float blockSum256(float v, float* sm, int lane, int wid)
{
#pragma unroll
    for (int o = 16; o; o >>= 1) v += __shfl_xor_sync(0xffffffffu, v, o);
    if (lane == 0) sm[wid] = v;
    __syncthreads();
    if (wid == 0) {
        float w = (lane < 8) ? sm[lane] : 0.f;
#pragma unroll
        for (int o = 4; o; o >>= 1) w += __shfl_xor_sync(0xffffffffu, w, o);
        if (lane == 0) sm[0] = w;
    }
    __syncthreads();
    float r = sm[0];
    __syncthreads();
    return r;
}

__global__ void row_pipeline_kernel(const int* __restrict__ mask,
                                    const float* __restrict__ gammas)
{
    __shared__ float sred[8];
    __shared__ float swarp[8];
    const int t = threadIdx.x;
    const int lane = t & 31, wid = t >> 5;
    const int row = blockIdx.x;              // (b*H + h)*S + i
    const int i  = row & (S - 1);
    const int bh = row >> 10;
    const int h  = bh % H;
    const int b  = bh / H;
    float* srow = g_scores + (size_t)row * S;
    const int j0 = t * 4;

    float4 x4 = *reinterpret_cast<const float4*>(srow + j0);
    float x[4] = { x4.x, x4.y, x4.z, x4.w };
    const int* mr = mask + b * S;
    int am[4];
#pragma unroll
    for (int u = 0; u < 4; u++) am[u] = mr[j0 + u] != 0;
    float xm[4];
#pragma unroll
    for (int u = 0; u < 4; u++) xm[u] = am[u] ? x[u] : -1e8f;

    float mx = fmaxf(fmaxf(xm[0], xm[1]), fmaxf(xm[2], xm[3]));
    mx = blockMax256(mx, sred, lane, wid);
    float e[4], le = 0.f;
#pragma unroll
    for (int u = 0; u < 4; u++) { e[u] = expf(xm[u] - mx); le += e[u]; }
    float denom = blockSum256(le, sred, lane, wid);
    float inv = 1.f / denom;
    float p[4];
#pragma unroll
    for (int u = 0; u < 4; u++) p[u] = am[u] ? e[u] * inv : 0.f;

    float lp[4]; float run = 0.f;
#pragma unroll
    for (int u = 0; u < 4; u++) { run += p[u]; lp[u] = run; }
    float tot = run;
    float sc = tot;
#pragma unroll
    for (int o = 1; o < 32; o <<= 1) {
        float v = __shfl_up_sync(0xffffffffu, sc, o);
        if (lane >= o) sc += v;
    }
    if (lane == 31) swarp[wid] = sc;
    __syncthreads();
    if (wid == 0) {
        float v = (lane < 8) ? swarp[lane] : 0.f;
#pragma unroll
        for (int o = 1; o < 8; o <<= 1) {
            float w = __shfl_up_sync(0xffffffffu, v, o);
            if (lane >= o) v += w;
        }
        if (lane < 8) swarp[lane] = v;
    }
    __syncthreads();
    float off = ((wid > 0) ? swarp[wid - 1] : 0.f) + (sc - tot);
    float total = swarp[7];
    __syncthreads();

    const float g0 = gammas[h];
    const float gamma = -(g0 > 20.f ? g0 : log1pf(expf(g0)));
    const float* tdr = g_tdsm + b * S;

    float y[4];
#pragma unroll
    for (int u = 0; u < 4; u++) {
        int j = j0 + u;
        float cum = off + lp[u];
        float rem = total - cum;
        float pos = fabsf((float)(j - i));
        float ds = sqrtf(fmaxf(rem * pos, 0.f));
        float te = expf(ds * gamma);
        te = fminf(fmaxf(te, 1e-5f), 1e5f);
        float tef = te - ((j < i) ? tdr[j] : 0.f);
        y[u] = am[u] ? x[u] * tef : -1e8f;
    }

    float mx2 = fmaxf(fmaxf(y[0], y[1]), fmaxf(y[2], y[3]));
    mx2 = blockMax256(mx2, sred, lane, wid);
    float e2[4], le2 = 0.f;
#pragma unroll
    for (int u = 0; u < 4; u++) { e2[u] = expf(y[u] - mx2); le2 += e2[u]; }
    float denom2 = blockSum256(le2, sred, lane, wid);
    float inv2 = 1.f / denom2;
    float4 o4;
    o4.x = e2[0] * inv2; o4.y = e2[1] * inv2; o4.z = e2[2] * inv2; o4.w = e2[3] * inv2;
    *reinterpret_cast<float4*>(srow + j0) = o4;
}

// ---------------- launcher ----------------
extern "C" void kernel_launch(void* const* d_in, const int* in_sizes, int n_in,
                              void* d_out, int out_size)
{
    const float* Q    = (const float*)d_in[0];
    const float* Kin  = (const float*)d_in[1];
    const float* V    = (const float*)d_in[2];
    const float* td   = (const float*)d_in[3];
    const int*   mask = (const int*)  d_in[4];
    const float* Wq   = (const float*)d_in[5];
    const float* Wk   = (const float*)d_in[6];
    const float* Wv   = (const float*)d_in[7];
    const float* dw_w = (const float*)d_in[8];
    const float* pw_w = (const float*)d_in[9];
    const float* sep_b= (const float*)d_in[10];
    const float* ck_W = (const float*)d_in[11];
    const float* ck_b = (const float*)d_in[12];
    const float* co_W = (const float*)d_in[13];
    const float* co_b = (const float*)d_in[14];
    const float* gammas=(const float*)d_in[15];
    float* out = (float*)d_out;

    float *p_scores, *p_mq, *p_mk, *p_mv, *p_co, *p_ca, *p_dw, *p_ck, *p_ckWp;
    cudaGetSymbolAddress((void**)&p_scores, g_scores);
    cudaGetSymbolAddress((void**)&p_mq, g_mq);
    cudaGetSymbolAddress((void**)&p_mk, g_mk);
    cudaGetSymbolAddress((void**)&p_mv, g_mv);
    cudaGetSymbolAddress((void**)&p_co, g_co);
    cudaGetSymbolAddress((void**)&p_ca, g_convattn);
    cudaGetSymbolAddress((void**)&p_dw, g_dw);
    cudaGetSymbolAddress((void**)&p_ck, g_ck);
    cudaGetSymbolAddress((void**)&p_ckWp, g_ckWp);

    cudaFuncSetAttribute(tf32_gemm_pipe<true>,  cudaFuncAttributeMaxDynamicSharedMemorySize, PIPE_SMEM);
    cudaFuncSetAttribute(tf32_gemm_pipe<false>, cudaFuncAttributeMaxDynamicSharedMemorySize, PIPE_SMEM);
    cudaFuncSetAttribute(tf32_proj5,            cudaFuncAttributeMaxDynamicSharedMemorySize, PIPE_SMEM);

    const int M = BB * S;   // 4096

    // independent prep
    tdsm_kernel<<<BB, 256>>>(td, mask);
    padW_kernel<<<(AH * 64 + 255) / 256, 256>>>(ck_W);
    {
        long long n = (long long)BB * S * HID;
        dw_kernel<<<(unsigned)((n + 255) / 256), 256>>>(Kin, dw_w);
    }

    // ---- 5 projections in ONE launch (z = op): Q, K, V, co, pw ----
    Proj5 pr;
    pr.A[0] = Q;    pr.B[0] = Wq;   pr.bias[0] = nullptr; pr.C[0] = p_mq; pr.bt[0] = 0; pr.ldb[0] = AH;
    pr.A[1] = Kin;  pr.B[1] = Wk;   pr.bias[1] = nullptr; pr.C[1] = p_mk; pr.bt[1] = 0; pr.ldb[1] = AH;
    pr.A[2] = V;    pr.B[2] = Wv;   pr.bias[2] = nullptr; pr.C[2] = p_mv; pr.bt[2] = 0; pr.ldb[2] = AH;
    pr.A[3] = V;    pr.B[3] = co_W; pr.bias[3] = co_b;    pr.C[3] = p_co; pr.bt[3] = 0; pr.ldb[3] = AH;
    pr.A[4] = p_dw; pr.B[4] = pw_w; pr.bias[4] = sep_b;   pr.C[4] = p_ca; pr.bt[4] = 1; pr.ldb[4] = HID;
    tf32_proj5<<<dim3(AH / 64, M / 128, 5), 256, PIPE_SMEM>>>(pr);

    // conv_attn = mkc * mq (in place)
    mul_kernel<<<(unsigned)(((long long)BB * S * AH / 4 + 255) / 256), 256>>>();

    // ck logits: [4096,384] @ [384,64] -> [4096,64] on tensor cores
    tf32_gemm_pipe<false><<<dim3(1, M / 128, 1), 256, PIPE_SMEM>>>(
        p_ca, p_ckWp, nullptr, nullptr, p_ck,
        64, AH, AH, 64, 64, 0, 0, 0, 0, 0, 0, 1, 1.f);

    // softmax + dynamic conv -> out[:, AH:2AH]
    convout_kernel<<<M, AH>>>(ck_b, out);

    // attention scores (batched over b,h)
    tf32_gemm_pipe<true><<<dim3(S / 64, S / 128, BB * H), 256, PIPE_SMEM>>>(
        p_mq, p_mk, nullptr, nullptr, p_scores,
        S, D, AH, AH, S,
        (long long)S * AH, (long long)D,
        (long long)S * AH, (long long)D,
        (long long)H * S * S, (long long)S * S,
        H, 0.125f);

    // fused dist_func + double softmax, in place
    row_pipeline_kernel<<<BB * H * S, 256>>>(mask, gammas);

    // ctx = probs @ v, written straight into first half of d_out
    tf32_gemm_pipe<false><<<dim3(D / 64, S / 128, BB * H), 256, PIPE_SMEM>>>(
        p_scores, p_mv, nullptr, nullptr, out,
        D, S, S, AH, OUT_W,
        (long long)H * S * S, (long long)S * S,
        (long long)S * AH, (long long)D,
        (long long)S * OUT_W, (long long)D,
        H, 1.f);
}

// round 8
// speedup vs baseline: 3.2239x; 1.0612x over previous
#include <cuda_runtime.h>
#include <cuda_bf16.h>
#include <math.h>

#define HID 768
#define NSPLITS 12
#define H 6
#define D 64
#define AH 384
#define KS 9
#define PAD 4
#define BB 4
#define S 1024
#define OUT_W 768
#define CKN 54      // H*KS

// ---------------- scratch (device globals; no allocation allowed) ----------------
__device__ float g_scores[(size_t)BB * H * S * S];     // reused for probs
__device__ float g_mq[(size_t)BB * S * AH];
__device__ float g_mk[(size_t)BB * S * AH];
__device__ float g_mv[(size_t)BB * S * AH];
__device__ float g_co[(size_t)BB * S * AH];
__device__ float g_convattn[(size_t)BB * S * AH];      // mkc, then *= mq in place
__device__ float g_dw[(size_t)BB * S * HID];
__device__ float g_tdsm[(size_t)BB * S];
__device__ float g_ck[(size_t)BB * S * 64];            // padded ck logits
__device__ float g_ckWp[(size_t)AH * 64];              // padded ck_W
__device__ float g_pv[(size_t)2 * BB * H * S * D];     // split-K partials

// ---------------- common helpers ----------------
__device__ __forceinline__ unsigned f2tf32(float x) {
    unsigned y;
    asm("cvt.rna.tf32.f32 %0, %1;" : "=r"(y) : "f"(x));
    return y;
}

__device__ __forceinline__ void mma8(float* c, const unsigned* a, const unsigned* b) {
    asm volatile("mma.sync.aligned.m16n8k8.row.col.f32.tf32.tf32.f32 "
        "{%0,%1,%2,%3},{%4,%5,%6,%7},{%8,%9},{%0,%1,%2,%3};"
        : "+f"(c[0]), "+f"(c[1]), "+f"(c[2]), "+f"(c[3])
        : "r"(a[0]), "r"(a[1]), "r"(a[2]), "r"(a[3]), "r"(b[0]), "r"(b[1]));
}

__device__ __forceinline__ unsigned smem_u32(const void* p) {
    return (unsigned)__cvta_generic_to_shared(p);
}
#define CP16(dst, src) asm volatile("cp.async.ca.shared.global [%0], [%1], 16;" :: "r"(dst), "l"(src))
#define CPCOMMIT()     asm volatile("cp.async.commit_group;")
#define CPWAIT(n)      asm volatile("cp.async.wait_group %0;" :: "n"(n))

// ================= pipelined TF32 GEMM, narrow core (BM128 x BN64) =================
#define PAS_LD 36
#define PBS_LDT 36   // BT: [n][k]
#define PBS_LDN 72   // !BT: [k][n]
#define PA_STG (128 * PAS_LD)
#define PB_STG (64 * PBS_LDT)
#define PIPE_SMEM ((2 * PA_STG + 2 * PB_STG) * 4)  // 55296 B

template<bool BT>
__device__ __forceinline__ void gemm_core_pipe(
    const float* __restrict__ A, const float* __restrict__ Bm,
    const float* __restrict__ bias, const float* __restrict__ mul,
    float* __restrict__ C, int N, int K, int lda, int ldb, int ldc, float alpha)
{
    extern __shared__ float dyn[];
    float* sA = dyn;
    float* sB = dyn + 2 * PA_STG;

    const int tid  = threadIdx.x;
    const int warp = tid >> 5, lane = tid & 31;
    const int g    = lane >> 2, tig = lane & 3;
    const int wm   = (warp >> 1) * 32, wn = (warp & 1) * 32;
    const int m0   = blockIdx.y * 128;
    const int n0   = blockIdx.x * 64;

    float acc[2][4][4];
#pragma unroll
    for (int mt = 0; mt < 2; mt++)
#pragma unroll
        for (int nt = 0; nt < 4; nt++)
#pragma unroll
            for (int e = 0; e < 4; e++) acc[mt][nt][e] = 0.f;

    const int nk = K >> 5;

    auto loadStage = [&](int ki, int st) {
        const int kbase = ki * 32;
#pragma unroll
        for (int it = 0; it < 4; it++) {
            int lin = tid + it * 256;
            int m = lin >> 3, kq = lin & 7;
            CP16(smem_u32(&sA[st * PA_STG + m * PAS_LD + kq * 4]),
                 A + (long long)(m0 + m) * lda + kbase + kq * 4);
        }
        if (BT) {
#pragma unroll
            for (int it = 0; it < 2; it++) {
                int lin = tid + it * 256;
                int n = lin >> 3, kq = lin & 7;
                CP16(smem_u32(&sB[st * PB_STG + n * PBS_LDT + kq * 4]),
                     Bm + (long long)(n0 + n) * ldb + kbase + kq * 4);
            }
        } else {
#pragma unroll
            for (int it = 0; it < 2; it++) {
                int lin = tid + it * 256;
                int k = lin >> 4, nq = lin & 15;
                CP16(smem_u32(&sB[st * PB_STG + k * PBS_LDN + nq * 4]),
                     Bm + (long long)(kbase + k) * ldb + n0 + nq * 4);
            }
        }
        CPCOMMIT();
    };

    loadStage(0, 0);
    for (int i = 0; i < nk; i++) {
        if (i + 1 < nk) { loadStage(i + 1, (i + 1) & 1); CPWAIT(1); }
        else            { CPWAIT(0); }
        __syncthreads();

        const float* as = &sA[(i & 1) * PA_STG];
        const float* bs = &sB[(i & 1) * PB_STG];
#pragma unroll
        for (int kk = 0; kk < 4; kk++) {
            const int kb = kk * 8;
            unsigned aF[2][4], bF[4][2];
#pragma unroll
            for (int mt = 0; mt < 2; mt++) {
                int mr = wm + mt * 16 + g;
                aF[mt][0] = f2tf32(as[mr * PAS_LD + kb + tig]);
                aF[mt][1] = f2tf32(as[(mr + 8) * PAS_LD + kb + tig]);
                aF[mt][2] = f2tf32(as[mr * PAS_LD + kb + tig + 4]);
                aF[mt][3] = f2tf32(as[(mr + 8) * PAS_LD + kb + tig + 4]);
            }
#pragma unroll
            for (int nt = 0; nt < 4; nt++) {
                int nc = wn + nt * 8 + g;
                if (BT) {
                    bF[nt][0] = f2tf32(bs[nc * PBS_LDT + kb + tig]);
                    bF[nt][1] = f2tf32(bs[nc * PBS_LDT + kb + tig + 4]);
                } else {
                    bF[nt][0] = f2tf32(bs[(kb + tig) * PBS_LDN + nc]);
                    bF[nt][1] = f2tf32(bs[(kb + tig + 4) * PBS_LDN + nc]);
                }
            }
#pragma unroll
            for (int mt = 0; mt < 2; mt++)
#pragma unroll
                for (int nt = 0; nt < 4; nt++)
                    mma8(acc[mt][nt], aF[mt], bF[nt]);
        }
        __syncthreads();
    }

#pragma unroll
    for (int mt = 0; mt < 2; mt++) {
#pragma unroll
        for (int nt = 0; nt < 4; nt++) {
            int gm0 = m0 + wm + mt * 16 + g;
            int gn0 = n0 + wn + nt * 8 + tig * 2;
            float* c = acc[mt][nt];
#pragma unroll
            for (int e = 0; e < 4; e++) {
                int gm = gm0 + (e >> 1) * 8;
                int gn = gn0 + (e & 1);
                float v = c[e] * alpha;
                if (bias) v += bias[gn];
                if (mul)  v *= mul[(long long)gm * ldc + gn];
                C[(long long)gm * ldc + gn] = v;
            }
        }
    }
}

// ================= wide core (BM128 x BN128), 8 warps of 32x64 =================
#define WAS_LD 36
#define WBS_LDT 36    // BT: [n][k]
#define WBS_LDN 136   // !BT: [k][n], 128+8 pad
#define WA_STG (128 * WAS_LD)     // 4608
#define WB_STG (128 * WBS_LDT)    // 4608 (covers !BT's 32*136=4352 too)
#define WIDE_SMEM ((2 * WA_STG + 2 * WB_STG) * 4)  // 73728 B

template<bool BT>
__device__ __forceinline__ void gemm_core_wide(
    const float* __restrict__ A, const float* __restrict__ Bm,
    const float* __restrict__ bias, float* __restrict__ C,
    int K, int lda, int ldb, int ldc, float alpha)
{
    extern __shared__ float dyn[];
    float* sA = dyn;
    float* sB = dyn + 2 * WA_STG;

    const int tid  = threadIdx.x;
    const int warp = tid >> 5, lane = tid & 31;
    const int g    = lane >> 2, tig = lane & 3;
    const int wm   = (warp >> 1) * 32, wn = (warp & 1) * 64;
    const int m0   = blockIdx.y * 128;
    const int n0   = blockIdx.x * 128;

    float acc[2][8][4];
#pragma unroll
    for (int mt = 0; mt < 2; mt++)
#pragma unroll
        for (int nt = 0; nt < 8; nt++)
#pragma unroll
            for (int e = 0; e < 4; e++) acc[mt][nt][e] = 0.f;

    const int nk = K >> 5;

    auto loadStage = [&](int ki, int st) {
        const int kbase = ki * 32;
#pragma unroll
        for (int it = 0; it < 4; it++) {
            int lin = tid + it * 256;
            int m = lin >> 3, kq = lin & 7;
            CP16(smem_u32(&sA[st * WA_STG + m * WAS_LD + kq * 4]),
                 A + (long long)(m0 + m) * lda + kbase + kq * 4);
        }
        if (BT) {
#pragma unroll
            for (int it = 0; it < 4; it++) {
                int lin = tid + it * 256;
                int n = lin >> 3, kq = lin & 7;
                CP16(smem_u32(&sB[st * WB_STG + n * WBS_LDT + kq * 4]),
                     Bm + (long long)(n0 + n) * ldb + kbase + kq * 4);
            }
        } else {
#pragma unroll
            for (int it = 0; it < 4; it++) {
                int lin = tid + it * 256;
                int k = lin >> 5, nq = lin & 31;
                CP16(smem_u32(&sB[st * WB_STG + k * WBS_LDN + nq * 4]),
                     Bm + (long long)(kbase + k) * ldb + n0 + nq * 4);
            }
        }
        CPCOMMIT();
    };

    loadStage(0, 0);
    for (int i = 0; i < nk; i++) {
        if (i + 1 < nk) { loadStage(i + 1, (i + 1) & 1); CPWAIT(1); }
        else            { CPWAIT(0); }
        __syncthreads();

        const float* as = &sA[(i & 1) * WA_STG];
        const float* bs = &sB[(i & 1) * WB_STG];
#pragma unroll
        for (int kk = 0; kk < 4; kk++) {
            const int kb = kk * 8;
            unsigned aF[2][4], bF[8][2];
#pragma unroll
            for (int mt = 0; mt < 2; mt++) {
                int mr = wm + mt * 16 + g;
                aF[mt][0] = f2tf32(as[mr * WAS_LD + kb + tig]);
                aF[mt][1] = f2tf32(as[(mr + 8) * WAS_LD + kb + tig]);
                aF[mt][2] = f2tf32(as[mr * WAS_LD + kb + tig + 4]);
                aF[mt][3] = f2tf32(as[(mr + 8) * WAS_LD + kb + tig + 4]);
            }
#pragma unroll
            for (int nt = 0; nt < 8; nt++) {
                int nc = wn + nt * 8 + g;
                if (BT) {
                    bF[nt][0] = f2tf32(bs[nc * WBS_LDT + kb + tig]);
                    bF[nt][1] = f2tf32(bs[nc * WBS_LDT + kb + tig + 4]);
                } else {
                    bF[nt][0] = f2tf32(bs[(kb + tig) * WBS_LDN + nc]);
                    bF[nt][1] = f2tf32(bs[(kb + tig + 4) * WBS_LDN + nc]);
                }
            }
#pragma unroll
            for (int mt = 0; mt < 2; mt++)
#pragma unroll
                for (int nt = 0; nt < 8; nt++)
                    mma8(acc[mt][nt], aF[mt], bF[nt]);
        }
        __syncthreads();
    }

#pragma unroll
    for (int mt = 0; mt < 2; mt++) {
#pragma unroll
        for (int nt = 0; nt < 8; nt++) {
            int gm0 = m0 + wm + mt * 16 + g;
            int gn0 = n0 + wn + nt * 8 + tig * 2;
            float* c = acc[mt][nt];
#pragma unroll
            for (int e = 0; e < 4; e++) {
                int gm = gm0 + (e >> 1) * 8;
                int gn = gn0 + (e & 1);
                float v = c[e] * alpha;
                if (bias) v += bias[gn];
                C[(long long)gm * ldc + gn] = v;
            }
        }
    }
}

// ---- 5 projections (Q,K,V,co,pw) in a single wide launch ----
struct Proj5 {
    const float* A[5];
    const float* B[5];
    const float* bias[5];
    float* C[5];
    int bt[5];
    int ldb[5];
};

__global__ __launch_bounds__(256) void tf32_proj5_w(Proj5 p)
{
    int op = blockIdx.z;
    if (p.bt[op])
        gemm_core_wide<true>(p.A[op], p.B[op], p.bias[op], p.C[op],
                             HID, HID, p.ldb[op], AH, 1.f);
    else
        gemm_core_wide<false>(p.A[op], p.B[op], p.bias[op], p.C[op],
                              HID, HID, p.ldb[op], AH, 1.f);
}

// ---- scores GEMM (wide, BT): per (b,h) batch ----
__global__ __launch_bounds__(256) void scores_kernel_w(
    const float* __restrict__ mq, const float* __restrict__ mk, float* __restrict__ scores)
{
    int z = blockIdx.z;
    int b = z / H, h = z % H;
    gemm_core_wide<true>(mq + (size_t)b * S * AH + h * D,
                         mk + (size_t)b * S * AH + h * D,
                         nullptr,
                         scores + (size_t)z * S * S,
                         D, AH, AH, S, 0.125f);
}

// ---- ck GEMM (narrow core) ----
__global__ __launch_bounds__(256) void ck_gemm_kernel(
    const float* __restrict__ ca, const float* __restrict__ ckWp, float* __restrict__ ck)
{
    gemm_core_pipe<false>(ca, ckWp, nullptr, nullptr, ck, 64, AH, AH, 64, 64, 1.f);
}

// ---- PV split-K (narrow core, N=64), z = bh*2 + kh ----
__global__ __launch_bounds__(256) void pv_split_kernel(
    const float* __restrict__ scores, const float* __restrict__ mv, float* __restrict__ pv)
{
    int z = blockIdx.z;
    int bh = z >> 1, kh = z & 1;
    int b = bh / H, h = bh % H;
    gemm_core_pipe<false>(scores + (size_t)bh * S * S + kh * 512,
                          mv + (size_t)b * S * AH + (size_t)(kh * 512) * AH + h * D,
                          nullptr, nullptr,
                          pv + (size_t)(kh * (BB * H) + bh) * S * D,
                          64, 512, S, AH, D, 1.f);
}

// ---- sum the two PV partials into d_out (interleaved ctx layout) ----
__global__ void pv_add_kernel(float* __restrict__ out)
{
    long long i4 = ((long long)blockIdx.x * blockDim.x + threadIdx.x) * 4;
    if (i4 >= (long long)BB * H * S * D) return;
    int d  = (int)(i4 & (D - 1));
    int s  = (int)((i4 >> 6) & (S - 1));
    int bh = (int)(i4 >> 16);
    int b = bh / H, h = bh % H;
    size_t p0 = (size_t)bh * S * D + (size_t)s * D + d;
    size_t p1 = p0 + (size_t)(BB * H) * S * D;
    float4 a = *reinterpret_cast<const float4*>(&g_pv[p0]);
    float4 c = *reinterpret_cast<const float4*>(&g_pv[p1]);
    a.x += c.x; a.y += c.y; a.z += c.z; a.w += c.w;
    *reinterpret_cast<float4*>(&out[((size_t)b * S + s) * OUT_W + h * D + d]) = a;
}

// ---------------- elementwise: g_convattn *= g_mq (float4) ----------------
__global__ void mul_kernel()
{
    long long i = ((long long)blockIdx.x * blockDim.x + threadIdx.x) * 4;
    if (i >= (long long)BB * S * AH) return;
    float4 a = *reinterpret_cast<const float4*>(&g_convattn[i]);
    float4 b = *reinterpret_cast<const float4*>(&g_mq[i]);
    a.x *= b.x; a.y *= b.y; a.z *= b.z; a.w *= b.w;
    *reinterpret_cast<float4*>(&g_convattn[i]) = a;
}

// ---------------- repack ck_W (384x54) -> g_ckWp (384x64, zero-padded) ----------------
__global__ void padW_kernel(const float* __restrict__ ckW)
{
    int i = blockIdx.x * blockDim.x + threadIdx.x;
    if (i >= AH * 64) return;
    int k = i >> 6, n = i & 63;
    g_ckWp[i] = (n < CKN) ? ckW[k * CKN + n] : 0.f;
}

// ---------------- dynamic span conv output (second half of d_out) ----------------
__global__ void convout_kernel(const float* __restrict__ ckb, float* __restrict__ out)
{
    __shared__ float s_ck[H * KS];
    const int bs = blockIdx.x;               // b*S + s
    const int b = bs >> 10, s = bs & (S - 1);
    const int t = threadIdx.x;               // 384
    __shared__ float s_log[H * KS];
    if (t < H * KS) s_log[t] = g_ck[(size_t)bs * 64 + t] + ckb[t];
    __syncthreads();
    if (t < H) {
        float mx = -3e38f;
#pragma unroll
        for (int k = 0; k < KS; k++) mx = fmaxf(mx, s_log[t * KS + k]);
        float sum = 0.f, ev[KS];
#pragma unroll
        for (int k = 0; k < KS; k++) { ev[k] = expf(s_log[t * KS + k] - mx); sum += ev[k]; }
        float inv = 1.f / sum;
#pragma unroll
        for (int k = 0; k < KS; k++) s_ck[t * KS + k] = ev[k] * inv;
    }
    __syncthreads();
    const int h = t >> 6;
    float acc = 0.f;
#pragma unroll
    for (int k = 0; k < KS; k++) {
        int sp = s + k - PAD;
        if (sp >= 0 && sp < S)
            acc = fmaf(s_ck[h * KS + k], g_co[((size_t)b * S + sp) * AH + t], acc);
    }
    out[((size_t)b * S + s) * OUT_W + AH + t] = acc;
}

// ---------------- depthwise conv over sequence dim ----------------
__global__ void dw_kernel(const float* __restrict__ Kin, const float* __restrict__ dw_w)
{
    long long idx = (long long)blockIdx.x * blockDim.x + threadIdx.x;
    if (idx >= (long long)BB * S * HID) return;
    int c  = (int)(idx % HID);
    long long bs = idx / HID;
    int s = (int)(bs % S);
    int b = (int)(bs / S);
    const float* kb = Kin + (long long)b * S * HID;
    float acc = 0.f;
#pragma unroll
    for (int t = 0; t < KS; t++) {
        int sp = s + t - PAD;
        if (sp >= 0 && sp < S) acc = fmaf(kb[(long long)sp * HID + c], dw_w[c * KS + t], acc);
    }
    g_dw[idx] = acc;
}

// ---------------- td softmax (row-independent) ----------------
__global__ void tdsm_kernel(const float* __restrict__ td, const int* __restrict__ mask)
{
    __shared__ float sred[8];
    const int b = blockIdx.x;
    const int t = threadIdx.x;
    const int lane = t & 31, wid = t >> 5;
    const int j0 = t * 4;
    const float* tr = td + b * S;
    const int* mr = mask + b * S;

    float v[4]; int am[4];
#pragma unroll
    for (int u = 0; u < 4; u++) { v[u] = tr[j0 + u]; am[u] = mr[j0 + u] != 0; }

    float ss = 0.f;
#pragma unroll
    for (int u = 0; u < 4; u++) ss += v[u] * v[u];
#pragma unroll
    for (int o = 16; o; o >>= 1) ss += __shfl_xor_sync(0xffffffffu, ss, o);
    if (lane == 0) sred[wid] = ss;
    __syncthreads();
    if (wid == 0) {
        float w = (lane < 8) ? sred[lane] : 0.f;
#pragma unroll
        for (int o = 4; o; o >>= 1) w += __shfl_xor_sync(0xffffffffu, w, o);
        if (lane == 0) sred[0] = w;
    }
    __syncthreads();
    float nrm = sqrtf(sred[0]);
    float inv = 1.f / fmaxf(nrm, 1e-12f);
    __syncthreads();

    float x[4];
#pragma unroll
    for (int u = 0; u < 4; u++) x[u] = am[u] ? v[u] * inv : -1e4f;

    float mx = fmaxf(fmaxf(x[0], x[1]), fmaxf(x[2], x[3]));
#pragma unroll
    for (int o = 16; o; o >>= 1) mx = fmaxf(mx, __shfl_xor_sync(0xffffffffu, mx, o));
    if (lane == 0) sred[wid] = mx;
    __syncthreads();
    if (wid == 0) {
        float w = (lane < 8) ? sred[lane] : -1e30f;
#pragma unroll
        for (int o = 4; o; o >>= 1) w = fmaxf(w, __shfl_xor_sync(0xffffffffu, w, o));
        if (lane == 0) sred[0] = w;
    }
    __syncthreads();
    mx = sred[0];
    __syncthreads();

    float e[4], le = 0.f;
#pragma unroll
    for (int u = 0; u < 4; u++) { e[u] = expf(x[u] - mx); le += e[u]; }
#pragma unroll
    for (int o = 16; o; o >>= 1) le += __shfl_xor_sync(0xffffffffu, le, o);
    if (lane == 0) sred[wid] = le;
    __syncthreads();
    if (wid == 0) {
        float w = (lane < 8) ? sred[lane] : 0.f;
#pragma unroll
        for (int o = 4; o; o >>= 1) w += __shfl_xor_sync(0xffffffffu, w, o);
        if (lane == 0) sred[0] = w;
    }
    __syncthreads();
    float dinv = 1.f / sred[0];
#pragma unroll
    for (int u = 0; u < 4; u++) g_tdsm[b * S + j0 + u] = e[u] * dinv;
}

// ---------------- fused per-row score pipeline ----------------
__device__ __forceinline__ float blockMax256(float v, float* sm, int lane, int wid)
{
#pragma unroll
    for (int o = 16; o; o >>= 1) v = fmaxf(v, __shfl_xor_sync(0xffffffffu, v, o));
    if (lane == 0) sm[wid] = v;
    __syncthreads();
    if (wid == 0) {
        float w = (lane < 8) ? sm[lane] : -3e38f;
#pragma unroll
        for (int o = 4; o; o >>= 1) w = fmaxf(w, __shfl_xor_sync(0xffffffffu, w, o));
        if (lane == 0) sm[0] = w;
    }
    __syncthreads();
    float r = sm[0];
    __syncthreads();
    return r;
}

__device__ __forceinline__ float blockSum256(float v, float* sm, int lane, int wid)
{
#pragma unroll
    for (int o = 16; o; o >>= 1) v += __shfl_xor_sync(0xffffffffu, v, o);
    if (lane == 0) sm[wid] = v;
    __syncthreads();
    if (wid == 0) {
        float w = (lane < 8) ? sm[lane] : 0.f;
#pragma unroll
        for (int o = 4; o; o >>= 1) w += __shfl_xor_sync(0xffffffffu, w, o);
        if (lane == 0) sm[0] = w;
    }
    __syncthreads();
    float r = sm[0];
    __syncthreads();
    return r;
}

__global__ void row_pipeline_kernel(const int* __restrict__ mask,
                                    const float* __restrict__ gammas)
{
    __shared__ float sred[8];
    __shared__ float swarp[8];
    const int t = threadIdx.x;
    const int lane = t & 31, wid = t >> 5;
    const int row = blockIdx.x;              // (b*H + h)*S + i
    const int i  = row & (S - 1);
    const int bh = row >> 10;
    const int h  = bh % H;
    const int b  = bh / H;
    float* srow = g_scores + (size_t)row * S;
    const int j0 = t * 4;

    float4 x4 = *reinterpret_cast<const float4*>(srow + j0);
    float x[4] = { x4.x, x4.y, x4.z, x4.w };
    const int* mr = mask + b * S;
    int am[4];
#pragma unroll
    for (int u = 0; u < 4; u++) am[u] = mr[j0 + u] != 0;
    float xm[4];
#pragma unroll
    for (int u = 0; u < 4; u++) xm[u] = am[u] ? x[u] : -1e8f;

    float mx = fmaxf(fmaxf(xm[0], xm[1]), fmaxf(xm[2], xm[3]));
    mx = blockMax256(mx, sred, lane, wid);
    float e[4], le = 0.f;
#pragma unroll
    for (int u = 0; u < 4; u++) { e[u] = expf(xm[u] - mx); le += e[u]; }
    float denom = blockSum256(le, sred, lane, wid);
    float inv = 1.f / denom;
    float p[4];
#pragma unroll
    for (int u = 0; u < 4; u++) p[u] = am[u] ? e[u] * inv : 0.f;

    float lp[4]; float run = 0.f;
#pragma unroll
    for (int u = 0; u < 4; u++) { run += p[u]; lp[u] = run; }
    float tot = run;
    float sc = tot;
#pragma unroll
    for (int o = 1; o < 32; o <<= 1) {
        float v = __shfl_up_sync(0xffffffffu, sc, o);
        if (lane >= o) sc += v;
    }
    if (lane == 31) swarp[wid] = sc;
    __syncthreads();
    if (wid == 0) {
        float v = (lane < 8) ? swarp[lane] : 0.f;
#pragma unroll
        for (int o = 1; o < 8; o <<= 1) {
            float w = __shfl_up_sync(0xffffffffu, v, o);
            if (lane >= o) v += w;
        }
        if (lane < 8) swarp[lane] = v;
    }
    __syncthreads();
    float off = ((wid > 0) ? swarp[wid - 1] : 0.f) + (sc - tot);
    float total = swarp[7];
    __syncthreads();

    const float g0 = gammas[h];
    const float gamma = -(g0 > 20.f ? g0 : log1pf(expf(g0)));
    const float* tdr = g_tdsm + b * S;

    float y[4];
#pragma unroll
    for (int u = 0; u < 4; u++) {
        int j = j0 + u;
        float cum = off + lp[u];
        float rem = total - cum;
        float pos = fabsf((float)(j - i));
        float ds = sqrtf(fmaxf(rem * pos, 0.f));
        float te = expf(ds * gamma);
        te = fminf(fmaxf(te, 1e-5f), 1e5f);
        float tef = te - ((j < i) ? tdr[j] : 0.f);
        y[u] = am[u] ? x[u] * tef : -1e8f;
    }

    float mx2 = fmaxf(fmaxf(y[0], y[1]), fmaxf(y[2], y[3]));
    mx2 = blockMax256(mx2, sred, lane, wid);
    float e2[4], le2 = 0.f;
#pragma unroll
    for (int u = 0; u < 4; u++) { e2[u] = expf(y[u] - mx2); le2 += e2[u]; }
    float denom2 = blockSum256(le2, sred, lane, wid);
    float inv2 = 1.f / denom2;
    float4 o4;
    o4.x = e2[0] * inv2; o4.y = e2[1] * inv2; o4.z = e2[2] * inv2; o4.w = e2[3] * inv2;
    *reinterpret_cast<float4*>(srow + j0) = o4;
}

// ---------------- launcher ----------------
extern "C" void kernel_launch(void* const* d_in, const int* in_sizes, int n_in,
                              void* d_out, int out_size)
{
    const float* Q    = (const float*)d_in[0];
    const float* Kin  = (const float*)d_in[1];
    const float* V    = (const float*)d_in[2];
    const float* td   = (const float*)d_in[3];
    const int*   mask = (const int*)  d_in[4];
    const float* Wq   = (const float*)d_in[5];
    const float* Wk   = (const float*)d_in[6];
    const float* Wv   = (const float*)d_in[7];
    const float* dw_w = (const float*)d_in[8];
    const float* pw_w = (const float*)d_in[9];
    const float* sep_b= (const float*)d_in[10];
    const float* ck_W = (const float*)d_in[11];
    const float* ck_b = (const float*)d_in[12];
    const float* co_W = (const float*)d_in[13];
    const float* co_b = (const float*)d_in[14];
    const float* gammas=(const float*)d_in[15];
    float* out = (float*)d_out;

    float *p_scores, *p_mq, *p_mk, *p_mv, *p_co, *p_ca, *p_dw, *p_ck, *p_ckWp, *p_pv;
    cudaGetSymbolAddress((void**)&p_scores, g_scores);
    cudaGetSymbolAddress((void**)&p_mq, g_mq);
    cudaGetSymbolAddress((void**)&p_mk, g_mk);
    cudaGetSymbolAddress((void**)&p_mv, g_mv);
    cudaGetSymbolAddress((void**)&p_co, g_co);
    cudaGetSymbolAddress((void**)&p_ca, g_convattn);
    cudaGetSymbolAddress((void**)&p_dw, g_dw);
    cudaGetSymbolAddress((void**)&p_ck, g_ck);
    cudaGetSymbolAddress((void**)&p_ckWp, g_ckWp);
    cudaGetSymbolAddress((void**)&p_pv, g_pv);

    cudaFuncSetAttribute(tf32_proj5_w,    cudaFuncAttributeMaxDynamicSharedMemorySize, WIDE_SMEM);
    cudaFuncSetAttribute(scores_kernel_w, cudaFuncAttributeMaxDynamicSharedMemorySize, WIDE_SMEM);
    cudaFuncSetAttribute(ck_gemm_kernel,  cudaFuncAttributeMaxDynamicSharedMemorySize, PIPE_SMEM);
    cudaFuncSetAttribute(pv_split_kernel, cudaFuncAttributeMaxDynamicSharedMemorySize, PIPE_SMEM);

    const int M = BB * S;   // 4096

    // independent prep
    tdsm_kernel<<<BB, 256>>>(td, mask);
    padW_kernel<<<(AH * 64 + 255) / 256, 256>>>(ck_W);
    {
        long long n = (long long)BB * S * HID;
        dw_kernel<<<(unsigned)((n + 255) / 256), 256>>>(Kin, dw_w);
    }

    // ---- 5 projections in ONE wide launch (z = op): Q, K, V, co, pw ----
    Proj5 pr;
    pr.A[0] = Q;    pr.B[0] = Wq;   pr.bias[0] = nullptr; pr.C[0] = p_mq; pr.bt[0] = 0; pr.ldb[0] = AH;
    pr.A[1] = Kin;  pr.B[1] = Wk;   pr.bias[1] = nullptr; pr.C[1] = p_mk; pr.bt[1] = 0; pr.ldb[1] = AH;
    pr.A[2] = V;    pr.B[2] = Wv;   pr.bias[2] = nullptr; pr.C[2] = p_mv; pr.bt[2] = 0; pr.ldb[2] = AH;
    pr.A[3] = V;    pr.B[3] = co_W; pr.bias[3] = co_b;    pr.C[3] = p_co; pr.bt[3] = 0; pr.ldb[3] = AH;
    pr.A[4] = p_dw; pr.B[4] = pw_w; pr.bias[4] = sep_b;   pr.C[4] = p_ca; pr.bt[4] = 1; pr.ldb[4] = HID;
    tf32_proj5_w<<<dim3(AH / 128, M / 128, 5), 256, WIDE_SMEM>>>(pr);

    // conv_attn = mkc * mq (in place)
    mul_kernel<<<(unsigned)(((long long)BB * S * AH / 4 + 255) / 256), 256>>>();

    // ck logits on tensor cores
    ck_gemm_kernel<<<dim3(1, M / 128, 1), 256, PIPE_SMEM>>>(p_ca, p_ckWp, p_ck);

    // softmax + dynamic conv -> out[:, AH:2AH]
    convout_kernel<<<M, AH>>>(ck_b, out);

    // attention scores (wide, batched over b,h)
    scores_kernel_w<<<dim3(S / 128, S / 128, BB * H), 256, WIDE_SMEM>>>(p_mq, p_mk, p_scores);

    // fused dist_func + double softmax, in place
    row_pipeline_kernel<<<BB * H * S, 256>>>(mask, gammas);

    // ctx = probs @ v with split-K=2, then sum into first half of d_out
    pv_split_kernel<<<dim3(1, S / 128, BB * H * 2), 256, PIPE_SMEM>>>(p_scores, p_mv, p_pv);
    pv_add_kernel<<<(unsigned)(((long long)BB * H * S * D / 4 + 255) / 256), 256>>>(out);
}